// round 12
// baseline (speedup 1.0000x reference)
#include <cuda_runtime.h>
#include <math.h>
#include <cstdint>

#define NN 20000
#define EE 320000
#define MMX (EE + NN)
#define FULL 0xffffffffu

// ---------------- scratch ----------------
__device__ float g_z[NN * 512];          // layer-1 aggregated z (pre-divided by sum)
__device__ float g_xa[NN * 128];
__device__ float g_s[NN * 4];
__device__ float g_d[NN * 4];
__device__ float g_h2[NN * 3];
__device__ int g_esrc[MMX];
__device__ int g_edst[MMX];
__device__ int g_deg[NN];
__device__ int g_rowptr[NN + 1];
__device__ int g_cursor[NN];
__device__ int g_csrs[MMX];              // CSR by dst: src node per slot
__device__ float g_A0[16];               // layer0: As(h,i) [0..7], Ad(h,i) [8..15]
__device__ float g_ws[512];              // layer1: w~s_h[k] = W1_h^T as_h
__device__ float g_wd[512];

// ---------------- accurate exp/expm1/elu ----------------
__device__ __forceinline__ float exp_acc(float x) {
    x = fminf(fmaxf(x, -87.0f), 87.0f);
    float kf = rintf(__fmul_rn(x, 1.4426950408889634f));
    float r = __fmaf_rn(kf, -0.69314718246459960938f, x);
    r = __fmaf_rn(kf, 1.9046542743622637e-9f, r);
    float p = 1.9841269841269841e-4f;
    p = __fmaf_rn(p, r, 1.3888888888888889e-3f);
    p = __fmaf_rn(p, r, 8.3333333333333332e-3f);
    p = __fmaf_rn(p, r, 4.1666666666666664e-2f);
    p = __fmaf_rn(p, r, 1.6666666666666666e-1f);
    p = __fmaf_rn(p, r, 0.5f);
    p = __fmaf_rn(p, r, 1.0f);
    p = __fmaf_rn(p, r, 1.0f);
    int ik = (int)kf;
    float s = __int_as_float((ik + 127) << 23);
    return __fmul_rn(p, s);
}
__device__ __forceinline__ float expm1_acc(float x) {
    if (x < -0.34657359f) return __fadd_rn(exp_acc(x), -1.0f);
    float p = 1.9841269841269841e-4f;
    p = __fmaf_rn(p, x, 1.3888888888888889e-3f);
    p = __fmaf_rn(p, x, 8.3333333333333332e-3f);
    p = __fmaf_rn(p, x, 4.1666666666666664e-2f);
    p = __fmaf_rn(p, x, 1.6666666666666666e-1f);
    p = __fmaf_rn(p, x, 0.5f);
    p = __fmaf_rn(p, x, 1.0f);
    return __fmul_rn(p, x);
}
__device__ __forceinline__ float elu_acc(float x) {
    return x > 0.f ? x : expm1_acc(x);
}
__device__ __forceinline__ float lrelu(float x) {
    return x >= 0.f ? x : 0.2f * x;
}
__device__ __forceinline__ float tf32r(float x) {
    float r;
    asm("cvt.rna.tf32.f32 %0, %1;" : "=f"(r) : "f"(x));
    return r;
}

// ---------------- warp mma: m16n8k8 tf32 ----------------
__device__ __forceinline__ void mma_tf32(float* c, const uint32_t* a, const uint32_t* b) {
    asm volatile(
        "mma.sync.aligned.m16n8k8.row.col.f32.tf32.tf32.f32 "
        "{%0,%1,%2,%3}, {%4,%5,%6,%7}, {%8,%9}, {%0,%1,%2,%3};"
        : "+f"(c[0]), "+f"(c[1]), "+f"(c[2]), "+f"(c[3])
        : "r"(a[0]), "r"(a[1]), "r"(a[2]), "r"(a[3]), "r"(b[0]), "r"(b[1]));
}

// ---------------- CSR build ----------------
__global__ void k_zero(int n) {
    int i = blockIdx.x * blockDim.x + threadIdx.x;
    if (i < n) g_deg[i] = 0;
}
__global__ void k_edges_count(const int* __restrict__ ei, int e, int m) {
    int i = blockIdx.x * blockDim.x + threadIdx.x;
    if (i >= m) return;
    int s, d;
    if (i < e) { s = ei[i]; d = ei[e + i]; }
    else       { s = i - e; d = i - e; }
    g_esrc[i] = s;
    g_edst[i] = d;
    atomicAdd(&g_deg[d], 1);
}
__global__ void k_scan(int n, int m) {
    __shared__ int wsum[32];
    int t = threadIdx.x;
    int lane = t & 31, wid = t >> 5;
    int chunk = (n + 1023) / 1024;
    int b0 = t * chunk;
    int b1 = min(b0 + chunk, n);
    int s = 0;
    for (int i = b0; i < b1; i++) s += g_deg[i];
    int v = s;
#pragma unroll
    for (int o = 1; o < 32; o <<= 1) {
        int u = __shfl_up_sync(FULL, v, o);
        if (lane >= o) v += u;
    }
    if (lane == 31) wsum[wid] = v;
    __syncthreads();
    if (wid == 0) {
        int w = wsum[lane];
#pragma unroll
        for (int o = 1; o < 32; o <<= 1) {
            int u = __shfl_up_sync(FULL, w, o);
            if (lane >= o) w += u;
        }
        wsum[lane] = w;
    }
    __syncthreads();
    int run = (v - s) + (wid > 0 ? wsum[wid - 1] : 0);
    for (int i = b0; i < b1; i++) {
        g_rowptr[i] = run;
        g_cursor[i] = run;
        run += g_deg[i];
    }
    if (t == 0) g_rowptr[n] = m;
}
__global__ void k_fill(int m) {
    int i = blockIdx.x * blockDim.x + threadIdx.x;
    if (i < m) {
        int pos = atomicAdd(&g_cursor[g_edst[i]], 1);
        g_csrs[pos] = g_esrc[i];
    }
}

// ---------------- precompute projected attention vectors ----------------
__global__ void k_pre(const float* __restrict__ W0, const float* __restrict__ as0,
                      const float* __restrict__ ad0,
                      const float* __restrict__ W1, const float* __restrict__ as1,
                      const float* __restrict__ ad1) {
    int t = threadIdx.x;
    if (t < 512) {
        int h = t >> 7, k = t & 127;
        float acc = 0.f;
        for (int c = 0; c < 128; c++)
            acc = __fmaf_rn(as1[h * 128 + c], W1[(size_t)(h * 128 + c) * 128 + k], acc);
        g_ws[t] = acc;
    } else {
        int u = t - 512;
        int h = u >> 7, k = u & 127;
        float acc = 0.f;
        for (int c = 0; c < 128; c++)
            acc = __fmaf_rn(ad1[h * 128 + c], W1[(size_t)(h * 128 + c) * 128 + k], acc);
        g_wd[u] = acc;
    }
    if (t < 16) {
        int h = t & 3, i = (t >> 2) & 1;
        const float* a = (t < 8) ? as0 : ad0;
        float acc = 0.f;
        for (int c = 0; c < 128; c++)
            acc = __fmaf_rn(a[h * 128 + c], W0[(h * 128 + c) * 2 + i], acc);
        g_A0[(t < 8 ? 0 : 8) + h * 2 + i] = acc;
    }
}

// ---------------- layer 0 scores ----------------
__global__ void k_score0(const float* __restrict__ x, int n) {
    int v = blockIdx.x * blockDim.x + threadIdx.x;
    if (v >= n) return;
    float x0 = x[2 * v], x1 = x[2 * v + 1];
    float4 s, d;
    s.x = __fmaf_rn(x0, g_A0[0], x1 * g_A0[1]);
    s.y = __fmaf_rn(x0, g_A0[2], x1 * g_A0[3]);
    s.z = __fmaf_rn(x0, g_A0[4], x1 * g_A0[5]);
    s.w = __fmaf_rn(x0, g_A0[6], x1 * g_A0[7]);
    d.x = __fmaf_rn(x0, g_A0[8],  x1 * g_A0[9]);
    d.y = __fmaf_rn(x0, g_A0[10], x1 * g_A0[11]);
    d.z = __fmaf_rn(x0, g_A0[12], x1 * g_A0[13]);
    d.w = __fmaf_rn(x0, g_A0[14], x1 * g_A0[15]);
    *(float4*)&g_s[v * 4] = s;
    *(float4*)&g_d[v * 4] = d;
}

// ---------------- layer 0: fused softmax + rank-2 aggregate + finalize ----------------
__global__ void k_l0agg(const float* __restrict__ x, const float* __restrict__ W0,
                        const float* __restrict__ bias,
                        const float* __restrict__ bng, const float* __restrict__ bnb,
                        const float* __restrict__ bnm, const float* __restrict__ bnv, int n) {
    int v = (blockIdx.x * blockDim.x + threadIdx.x) >> 5;
    int lane = threadIdx.x & 31;
    if (v >= n) return;
    int beg = g_rowptr[v], end = g_rowptr[v + 1];
    float4 dv = *(const float4*)&g_d[v * 4];

    float m0 = -1e30f, m1 = -1e30f, m2 = -1e30f, m3 = -1e30f;
    for (int idx = beg + lane; idx < end; idx += 32) {
        int s = g_csrs[idx];
        float4 sv = *(const float4*)&g_s[s * 4];
        m0 = fmaxf(m0, lrelu(sv.x + dv.x));
        m1 = fmaxf(m1, lrelu(sv.y + dv.y));
        m2 = fmaxf(m2, lrelu(sv.z + dv.z));
        m3 = fmaxf(m3, lrelu(sv.w + dv.w));
    }
#pragma unroll
    for (int o = 16; o > 0; o >>= 1) {
        m0 = fmaxf(m0, __shfl_xor_sync(FULL, m0, o));
        m1 = fmaxf(m1, __shfl_xor_sync(FULL, m1, o));
        m2 = fmaxf(m2, __shfl_xor_sync(FULL, m2, o));
        m3 = fmaxf(m3, __shfl_xor_sync(FULL, m3, o));
    }

    float s0 = 0.f, s1 = 0.f, s2 = 0.f, s3 = 0.f;
    float zx0 = 0.f, zx1 = 0.f, zx2 = 0.f, zx3 = 0.f;
    float zy0 = 0.f, zy1 = 0.f, zy2 = 0.f, zy3 = 0.f;
    for (int idx = beg + lane; idx < end; idx += 32) {
        int s = g_csrs[idx];
        float4 sv = *(const float4*)&g_s[s * 4];
        float p0 = exp_acc(lrelu(sv.x + dv.x) - m0);
        float p1 = exp_acc(lrelu(sv.y + dv.y) - m1);
        float p2 = exp_acc(lrelu(sv.z + dv.z) - m2);
        float p3 = exp_acc(lrelu(sv.w + dv.w) - m3);
        s0 += p0; s1 += p1; s2 += p2; s3 += p3;
        float2 xv = *(const float2*)&x[2 * s];
        zx0 = __fmaf_rn(p0, xv.x, zx0); zy0 = __fmaf_rn(p0, xv.y, zy0);
        zx1 = __fmaf_rn(p1, xv.x, zx1); zy1 = __fmaf_rn(p1, xv.y, zy1);
        zx2 = __fmaf_rn(p2, xv.x, zx2); zy2 = __fmaf_rn(p2, xv.y, zy2);
        zx3 = __fmaf_rn(p3, xv.x, zx3); zy3 = __fmaf_rn(p3, xv.y, zy3);
    }
#pragma unroll
    for (int o = 16; o > 0; o >>= 1) {
        s0 += __shfl_xor_sync(FULL, s0, o);  s1 += __shfl_xor_sync(FULL, s1, o);
        s2 += __shfl_xor_sync(FULL, s2, o);  s3 += __shfl_xor_sync(FULL, s3, o);
        zx0 += __shfl_xor_sync(FULL, zx0, o); zx1 += __shfl_xor_sync(FULL, zx1, o);
        zx2 += __shfl_xor_sync(FULL, zx2, o); zx3 += __shfl_xor_sync(FULL, zx3, o);
        zy0 += __shfl_xor_sync(FULL, zy0, o); zy1 += __shfl_xor_sync(FULL, zy1, o);
        zy2 += __shfl_xor_sync(FULL, zy2, o); zy3 += __shfl_xor_sync(FULL, zy3, o);
    }
    float d0 = __fadd_rn(s0, 1e-16f);
    float d1 = __fadd_rn(s1, 1e-16f);
    float d2 = __fadd_rn(s2, 1e-16f);
    float d3 = __fadd_rn(s3, 1e-16f);
    float ZX[4] = {zx0, zx1, zx2, zx3};
    float ZY[4] = {zy0, zy1, zy2, zy3};
    float DD[4] = {d0, d1, d2, d3};

    int c = lane * 4;
    float vals[4];
#pragma unroll
    for (int j = 0; j < 4; j++) {
        int cc = c + j;
        float a = 0.f;
#pragma unroll
        for (int h = 0; h < 4; h++) {
            float w0 = W0[(h * 128 + cc) * 2];
            float w1 = W0[(h * 128 + cc) * 2 + 1];
            float tmp = __fmaf_rn(w0, ZX[h], __fmul_rn(w1, ZY[h]));
            a = __fadd_rn(a, __fdiv_rn(tmp, DD[h]));
        }
        float val = __fmul_rn(a, 0.25f);
        val = __fadd_rn(val, bias[cc]);
        val = elu_acc(val);
        float inv = __frsqrt_rn(__fadd_rn(bnv[cc], 1e-5f));
        val = __fadd_rn(__fmul_rn(__fmul_rn(__fsub_rn(val, bnm[cc]), inv), bng[cc]), bnb[cc]);
        vals[j] = val;
    }
    *(float4*)&g_xa[(size_t)v * 128 + c] = make_float4(vals[0], vals[1], vals[2], vals[3]);
}

// ---------------- layer 1 scores ----------------
__global__ void k_score1(int n) {
    int v = (blockIdx.x * blockDim.x + threadIdx.x) >> 5;
    int lane = threadIdx.x & 31;
    if (v >= n) return;
    float4 xv = *(const float4*)&g_xa[(size_t)v * 128 + lane * 4];
    float sp[4], dp[4];
#pragma unroll
    for (int hd = 0; hd < 4; hd++) {
        float4 wv = *(const float4*)&g_ws[hd * 128 + lane * 4];
        float4 uv = *(const float4*)&g_wd[hd * 128 + lane * 4];
        float s = xv.x * wv.x + xv.y * wv.y + xv.z * wv.z + xv.w * wv.w;
        float d = xv.x * uv.x + xv.y * uv.y + xv.z * uv.z + xv.w * uv.w;
#pragma unroll
        for (int o = 16; o > 0; o >>= 1) {
            s += __shfl_xor_sync(FULL, s, o);
            d += __shfl_xor_sync(FULL, d, o);
        }
        sp[hd] = s;
        dp[hd] = d;
    }
    if (lane == 0) {
        *(float4*)&g_s[v * 4] = make_float4(sp[0], sp[1], sp[2], sp[3]);
        *(float4*)&g_d[v * 4] = make_float4(dp[0], dp[1], dp[2], dp[3]);
    }
}

// ---------------- layer 1: fused softmax + z-aggregate ----------------
__global__ void k_agg1(int n) {
    int v = (blockIdx.x * blockDim.x + threadIdx.x) >> 5;
    int lane = threadIdx.x & 31;
    if (v >= n) return;
    int beg = g_rowptr[v], end = g_rowptr[v + 1];
    float4 dv = *(const float4*)&g_d[v * 4];

    float m0 = -1e30f, m1 = -1e30f, m2 = -1e30f, m3 = -1e30f;
    for (int idx = beg + lane; idx < end; idx += 32) {
        int s = g_csrs[idx];
        float4 sv = *(const float4*)&g_s[s * 4];
        m0 = fmaxf(m0, lrelu(sv.x + dv.x));
        m1 = fmaxf(m1, lrelu(sv.y + dv.y));
        m2 = fmaxf(m2, lrelu(sv.z + dv.z));
        m3 = fmaxf(m3, lrelu(sv.w + dv.w));
    }
#pragma unroll
    for (int o = 16; o > 0; o >>= 1) {
        m0 = fmaxf(m0, __shfl_xor_sync(FULL, m0, o));
        m1 = fmaxf(m1, __shfl_xor_sync(FULL, m1, o));
        m2 = fmaxf(m2, __shfl_xor_sync(FULL, m2, o));
        m3 = fmaxf(m3, __shfl_xor_sync(FULL, m3, o));
    }

    float acc[16];
#pragma unroll
    for (int i = 0; i < 16; i++) acc[i] = 0.f;
    float s0 = 0.f, s1 = 0.f, s2 = 0.f, s3 = 0.f;

    for (int base = beg; base < end; base += 32) {
        int idx = base + lane;
        int sv = 0;
        float p0 = 0.f, p1 = 0.f, p2 = 0.f, p3 = 0.f;
        if (idx < end) {
            sv = g_csrs[idx];
            float4 ss = *(const float4*)&g_s[sv * 4];
            p0 = exp_acc(lrelu(ss.x + dv.x) - m0);
            p1 = exp_acc(lrelu(ss.y + dv.y) - m1);
            p2 = exp_acc(lrelu(ss.z + dv.z) - m2);
            p3 = exp_acc(lrelu(ss.w + dv.w) - m3);
            s0 += p0; s1 += p1; s2 += p2; s3 += p3;
        }
        int cnt = min(32, end - base);
        for (int t = 0; t < cnt; t++) {
            int s = __shfl_sync(FULL, sv, t);
            float q0 = __shfl_sync(FULL, p0, t);
            float q1 = __shfl_sync(FULL, p1, t);
            float q2 = __shfl_sync(FULL, p2, t);
            float q3 = __shfl_sync(FULL, p3, t);
            float4 xv = *(const float4*)&g_xa[(size_t)s * 128 + lane * 4];
            acc[0]  = __fmaf_rn(q0, xv.x, acc[0]);  acc[1]  = __fmaf_rn(q0, xv.y, acc[1]);
            acc[2]  = __fmaf_rn(q0, xv.z, acc[2]);  acc[3]  = __fmaf_rn(q0, xv.w, acc[3]);
            acc[4]  = __fmaf_rn(q1, xv.x, acc[4]);  acc[5]  = __fmaf_rn(q1, xv.y, acc[5]);
            acc[6]  = __fmaf_rn(q1, xv.z, acc[6]);  acc[7]  = __fmaf_rn(q1, xv.w, acc[7]);
            acc[8]  = __fmaf_rn(q2, xv.x, acc[8]);  acc[9]  = __fmaf_rn(q2, xv.y, acc[9]);
            acc[10] = __fmaf_rn(q2, xv.z, acc[10]); acc[11] = __fmaf_rn(q2, xv.w, acc[11]);
            acc[12] = __fmaf_rn(q3, xv.x, acc[12]); acc[13] = __fmaf_rn(q3, xv.y, acc[13]);
            acc[14] = __fmaf_rn(q3, xv.z, acc[14]); acc[15] = __fmaf_rn(q3, xv.w, acc[15]);
        }
    }
#pragma unroll
    for (int o = 16; o > 0; o >>= 1) {
        s0 += __shfl_xor_sync(FULL, s0, o);
        s1 += __shfl_xor_sync(FULL, s1, o);
        s2 += __shfl_xor_sync(FULL, s2, o);
        s3 += __shfl_xor_sync(FULL, s3, o);
    }
    float r0 = __fdiv_rn(1.0f, __fadd_rn(s0, 1e-16f));
    float r1 = __fdiv_rn(1.0f, __fadd_rn(s1, 1e-16f));
    float r2 = __fdiv_rn(1.0f, __fadd_rn(s2, 1e-16f));
    float r3 = __fdiv_rn(1.0f, __fadd_rn(s3, 1e-16f));

    float* zp = &g_z[(size_t)v * 512 + lane * 4];
    *(float4*)&zp[0]   = make_float4(acc[0] * r0,  acc[1] * r0,  acc[2] * r0,  acc[3] * r0);
    *(float4*)&zp[128] = make_float4(acc[4] * r1,  acc[5] * r1,  acc[6] * r1,  acc[7] * r1);
    *(float4*)&zp[256] = make_float4(acc[8] * r2,  acc[9] * r2,  acc[10] * r2, acc[11] * r2);
    *(float4*)&zp[384] = make_float4(acc[12] * r3, acc[13] * r3, acc[14] * r3, acc[15] * r3);
}

// ---------------- layer 1: mma.sync TF32 (3xTF32, R10 structure) + fused layer-2 head ----
// val[v][c] = BN(ELU(0.25 * sum_{K=512} z~[v][k]*Wcat[c][k] + b1[c]))  (never stored)
// h2[v][o] = sum_c val[v][c] * W2[o*128+c];  g_s/g_d from as2/ad2.
#define STR 36
#define SM_AH 0
#define SM_AL (128 * STR)
#define SM_BH (2 * 128 * STR)
#define SM_BL (3 * 128 * STR)
#define MMA_SMEM (4 * 128 * STR * 4)

__global__ void k_gemm_mma(const float* __restrict__ W1, const float* __restrict__ bias,
                           const float* __restrict__ bng, const float* __restrict__ bnb,
                           const float* __restrict__ bnm, const float* __restrict__ bnv,
                           const float* __restrict__ W2, const float* __restrict__ as2,
                           const float* __restrict__ ad2, int n) {
    extern __shared__ float sm[];
    int tid = threadIdx.x;
    int wid = tid >> 5, lane = tid & 31;
    int warp_m = wid >> 2;          // 0..1  (64 rows each)
    int warp_n = wid & 3;           // 0..3  (32 cols each)
    int grp = lane >> 2;            // 0..7
    int tig = lane & 3;             // 0..3
    int node0 = blockIdx.x * 128;

    float acc[4][4][4];
#pragma unroll
    for (int mf = 0; mf < 4; mf++)
#pragma unroll
        for (int nf = 0; nf < 4; nf++)
#pragma unroll
            for (int q = 0; q < 4; q++) acc[mf][nf][q] = 0.f;

    for (int ck = 0; ck < 16; ck++) {
        // fill A: z~[node0+row][ck*32 + kl] split hi/lo
        for (int i = tid; i < 128 * 8; i += 256) {
            int row = i >> 3;
            int kl = (i & 7) * 4;
            int nd = node0 + row;
            float4 v = make_float4(0.f, 0.f, 0.f, 0.f);
            if (nd < n) v = *(const float4*)&g_z[(size_t)nd * 512 + ck * 32 + kl];
            float4 h4, l4;
            h4.x = tf32r(v.x); h4.y = tf32r(v.y); h4.z = tf32r(v.z); h4.w = tf32r(v.w);
            l4.x = v.x - h4.x; l4.y = v.y - h4.y; l4.z = v.z - h4.z; l4.w = v.w - h4.w;
            *(float4*)&sm[SM_AH + row * STR + kl] = h4;
            *(float4*)&sm[SM_AL + row * STR + kl] = l4;
        }
        // fill B: Wcat[c][ck*32 + kl] = W1[(h*128+c)*128 + kk], h=ck>>2, kk=(ck&3)*32+kl
        {
            int h = ck >> 2, kb = (ck & 3) * 32;
            for (int i = tid; i < 128 * 8; i += 256) {
                int row = i >> 3;
                int kl = (i & 7) * 4;
                float4 v = *(const float4*)&W1[(size_t)(h * 128 + row) * 128 + kb + kl];
                float4 h4, l4;
                h4.x = tf32r(v.x); h4.y = tf32r(v.y); h4.z = tf32r(v.z); h4.w = tf32r(v.w);
                l4.x = v.x - h4.x; l4.y = v.y - h4.y; l4.z = v.z - h4.z; l4.w = v.w - h4.w;
                *(float4*)&sm[SM_BH + row * STR + kl] = h4;
                *(float4*)&sm[SM_BL + row * STR + kl] = l4;
            }
        }
        __syncthreads();

#pragma unroll
        for (int k8 = 0; k8 < 4; k8++) {
            int k0 = k8 * 8;
            uint32_t ah[4][4], al[4][4], bh[4][2], bl[4][2];
#pragma unroll
            for (int mf = 0; mf < 4; mf++) {
                int r0 = warp_m * 64 + mf * 16;
                ah[mf][0] = __float_as_uint(sm[SM_AH + (r0 + grp) * STR + k0 + tig]);
                ah[mf][1] = __float_as_uint(sm[SM_AH + (r0 + grp + 8) * STR + k0 + tig]);
                ah[mf][2] = __float_as_uint(sm[SM_AH + (r0 + grp) * STR + k0 + tig + 4]);
                ah[mf][3] = __float_as_uint(sm[SM_AH + (r0 + grp + 8) * STR + k0 + tig + 4]);
                al[mf][0] = __float_as_uint(sm[SM_AL + (r0 + grp) * STR + k0 + tig]);
                al[mf][1] = __float_as_uint(sm[SM_AL + (r0 + grp + 8) * STR + k0 + tig]);
                al[mf][2] = __float_as_uint(sm[SM_AL + (r0 + grp) * STR + k0 + tig + 4]);
                al[mf][3] = __float_as_uint(sm[SM_AL + (r0 + grp + 8) * STR + k0 + tig + 4]);
            }
#pragma unroll
            for (int nf = 0; nf < 4; nf++) {
                int c0 = warp_n * 32 + nf * 8;
                bh[nf][0] = __float_as_uint(sm[SM_BH + (c0 + grp) * STR + k0 + tig]);
                bh[nf][1] = __float_as_uint(sm[SM_BH + (c0 + grp) * STR + k0 + tig + 4]);
                bl[nf][0] = __float_as_uint(sm[SM_BL + (c0 + grp) * STR + k0 + tig]);
                bl[nf][1] = __float_as_uint(sm[SM_BL + (c0 + grp) * STR + k0 + tig + 4]);
            }
#pragma unroll
            for (int mf = 0; mf < 4; mf++)
#pragma unroll
                for (int nf = 0; nf < 4; nf++) {
                    mma_tf32(acc[mf][nf], ah[mf], bh[nf]);
                    mma_tf32(acc[mf][nf], ah[mf], bl[nf]);
                    mma_tf32(acc[mf][nf], al[mf], bh[nf]);
                }
        }
        __syncthreads();
    }

    // ---- fused epilogue: finalize vals, reduce h2 = val . W2^T into smem ----
    float* h2s = sm;                 // reuse buffers: 128 rows x 4 floats
    for (int i = tid; i < 512; i += 256) h2s[i] = 0.f;
    __syncthreads();

#pragma unroll
    for (int mf = 0; mf < 4; mf++) {
#pragma unroll
        for (int half = 0; half < 2; half++) {
            int row_local = warp_m * 64 + mf * 16 + grp + half * 8;
            float p0 = 0.f, p1 = 0.f, p2 = 0.f;
#pragma unroll
            for (int nf = 0; nf < 4; nf++) {
                int c0 = warp_n * 32 + nf * 8 + tig * 2;
#pragma unroll
                for (int q = 0; q < 2; q++) {
                    int c = c0 + q;
                    float val = __fmul_rn(acc[mf][nf][half * 2 + q], 0.25f);
                    val = __fadd_rn(val, bias[c]);
                    val = elu_acc(val);
                    float inv = __frsqrt_rn(__fadd_rn(bnv[c], 1e-5f));
                    val = __fadd_rn(__fmul_rn(__fmul_rn(__fsub_rn(val, bnm[c]), inv), bng[c]), bnb[c]);
                    p0 = __fmaf_rn(val, W2[c], p0);
                    p1 = __fmaf_rn(val, W2[128 + c], p1);
                    p2 = __fmaf_rn(val, W2[256 + c], p2);
                }
            }
            atomicAdd(&h2s[row_local * 4 + 0], p0);
            atomicAdd(&h2s[row_local * 4 + 1], p1);
            atomicAdd(&h2s[row_local * 4 + 2], p2);
        }
    }
    __syncthreads();

    if (tid < 128) {
        int nd = node0 + tid;
        if (nd < n) {
            float h0 = h2s[tid * 4 + 0];
            float h1 = h2s[tid * 4 + 1];
            float h2v = h2s[tid * 4 + 2];
            g_h2[nd * 3 + 0] = h0;
            g_h2[nd * 3 + 1] = h1;
            g_h2[nd * 3 + 2] = h2v;
            g_s[nd] = __fmaf_rn(h0, as2[0], __fmaf_rn(h1, as2[1], h2v * as2[2]));
            g_d[nd] = __fmaf_rn(h0, ad2[0], __fmaf_rn(h1, ad2[1], h2v * ad2[2]));
        }
    }
}

// ---------------- layer 2: softmax + aggregate + ODE epilogue ----------------
__global__ void k_smax2epi(const float* __restrict__ b2,
                           const float* __restrict__ kk, const float* __restrict__ dd,
                           const float* __restrict__ t00, const float* __restrict__ u00,
                           const float* __restrict__ t, float* __restrict__ out, int n) {
    int v = (blockIdx.x * blockDim.x + threadIdx.x) >> 5;
    int lane = threadIdx.x & 31;
    if (v >= n) return;
    int beg = g_rowptr[v], end = g_rowptr[v + 1];
    float sd = g_d[v];

    float mx = -1e30f;
    for (int idx = beg + lane; idx < end; idx += 32)
        mx = fmaxf(mx, lrelu(g_s[g_csrs[idx]] + sd));
#pragma unroll
    for (int o = 16; o > 0; o >>= 1) mx = fmaxf(mx, __shfl_xor_sync(FULL, mx, o));

    float sum = 0.f, a0 = 0.f, a1 = 0.f, a2 = 0.f;
    for (int idx = beg + lane; idx < end; idx += 32) {
        int s = g_csrs[idx];
        float p = exp_acc(lrelu(g_s[s] + sd) - mx);
        sum += p;
        a0 = __fmaf_rn(p, g_h2[s * 3 + 0], a0);
        a1 = __fmaf_rn(p, g_h2[s * 3 + 1], a1);
        a2 = __fmaf_rn(p, g_h2[s * 3 + 2], a2);
    }
#pragma unroll
    for (int o = 16; o > 0; o >>= 1) {
        sum += __shfl_xor_sync(FULL, sum, o);
        a0 += __shfl_xor_sync(FULL, a0, o);
        a1 += __shfl_xor_sync(FULL, a1, o);
        a2 += __shfl_xor_sync(FULL, a2, o);
    }
    if (lane == 0) {
        float denom = __fadd_rn(sum, 1e-16f);
        float ar  = elu_acc(__fadd_rn(__fdiv_rn(a0, denom), b2[0]));
        float gam = elu_acc(__fadd_rn(__fdiv_rn(a1, denom), b2[1]));
        float bet = elu_acc(__fadd_rn(__fdiv_rn(a2, denom), b2[2]));

        float tt = t[v];
        float K = kk[0], D = dd[0], T0 = t00[0], U0 = u00[0];

        float z = __fmul_rn(K, __fsub_rn(__fsub_rn(tt, T0), D));
        float S = __fdiv_rn(1.0f, __fadd_rn(1.0f, exp_acc(-z)));
        float oneMS = __fsub_rn(1.0f, S);

        float eb  = exp_acc(__fmul_rn(-bet, tt));
        float eg  = exp_acc(__fmul_rn(-gam, tt));
        float tmt0 = __fsub_rn(tt, T0);
        float ebs = exp_acc(__fmul_rn(-bet, tmt0));
        float egs = exp_acc(__fmul_rn(-gam, tmt0));
        float ab = __fdiv_rn(ar, bet);
        float ag = __fdiv_rn(ar, gam);

        float tu = __fadd_rn(
                     __fadd_rn(__fmul_rn(__fmul_rn(ab, __fsub_rn(1.0f, eb)), oneMS),
                               __fmul_rn(ab, S)),
                     __fmul_rn(__fsub_rn(__fmul_rn(U0, ebs), ab), S));

        float gmb = __fsub_rn(gam, bet);
        float term1 = __fadd_rn(__fmul_rn(ag, __fsub_rn(1.0f, eg)),
                                __fmul_rn(__fdiv_rn(ar, gmb), __fsub_rn(eg, eb)));
        float term3 = __fmul_rn(__fmul_rn(__fdiv_rn(__fmul_rn(bet, U0), gmb),
                                          __fsub_rn(egs, ebs)), S);
        float ts = __fadd_rn(__fadd_rn(__fmul_rn(term1, oneMS), __fmul_rn(ag, S)), term3);

        out[v] = tu;
        out[n + v] = ts;
    }
}

// ---------------- launch ----------------
extern "C" void kernel_launch(void* const* d_in, const int* in_sizes, int n_in,
                              void* d_out, int out_size) {
    int off = (n_in >= 28) ? 0 : -1;
    const float* x    = (const float*)d_in[0];
    const int*   ei   = (const int*)d_in[1];
    const float* W0   = (const float*)d_in[3 + off];
    const float* as0  = (const float*)d_in[4 + off];
    const float* ad0  = (const float*)d_in[5 + off];
    const float* b0   = (const float*)d_in[6 + off];
    const float* W1   = (const float*)d_in[7 + off];
    const float* as1  = (const float*)d_in[8 + off];
    const float* ad1  = (const float*)d_in[9 + off];
    const float* b1   = (const float*)d_in[10 + off];
    const float* W2   = (const float*)d_in[11 + off];
    const float* as2  = (const float*)d_in[12 + off];
    const float* ad2  = (const float*)d_in[13 + off];
    const float* b2   = (const float*)d_in[14 + off];
    const float* bng0 = (const float*)d_in[15 + off];
    const float* bnb0 = (const float*)d_in[16 + off];
    const float* bnm0 = (const float*)d_in[17 + off];
    const float* bnv0 = (const float*)d_in[18 + off];
    const float* bng1 = (const float*)d_in[19 + off];
    const float* bnb1 = (const float*)d_in[20 + off];
    const float* bnm1 = (const float*)d_in[21 + off];
    const float* bnv1 = (const float*)d_in[22 + off];
    const float* kk   = (const float*)d_in[23 + off];
    const float* dd   = (const float*)d_in[24 + off];
    const float* t00  = (const float*)d_in[25 + off];
    const float* u00  = (const float*)d_in[26 + off];
    const float* t    = (const float*)d_in[27 + off];
    float* out = (float*)d_out;

    int n = in_sizes[0] / 2;
    int e = in_sizes[1] / 2;
    int m = e + n;

    const int B = 256;
    auto nb = [](long long x_, int b) { return (int)((x_ + b - 1) / b); };
    int nwb = nb((long long)n * 32, B);   // warp-per-node grids

    cudaFuncSetAttribute(k_gemm_mma, cudaFuncAttributeMaxDynamicSharedMemorySize, MMA_SMEM);

    // CSR build + attention-vector precompute
    k_zero<<<nb(n, B), B>>>(n);
    k_edges_count<<<nb(m, B), B>>>(ei, e, m);
    k_scan<<<1, 1024>>>(n, m);
    k_fill<<<nb(m, B), B>>>(m);
    k_pre<<<1, 1024>>>(W0, as0, ad0, W1, as1, ad1);

    // ---- layer 0 (h never materialized) ----
    k_score0<<<nb(n, B), B>>>(x, n);
    k_l0agg<<<nwb, B>>>(x, W0, b0, bng0, bnb0, bnm0, bnv0, n);

    // ---- layer 1 (aggregate z first, project after on tensor cores; layer-2 head fused) ----
    k_score1<<<nwb, B>>>(n);
    k_agg1<<<nwb, B>>>(n);
    k_gemm_mma<<<nb(n, 128), 256, MMA_SMEM>>>(W1, b1, bng1, bnb1, bnm1, bnv1,
                                              W2, as2, ad2, n);

    // ---- layer 2 aggregation + epilogue ----
    k_smax2epi<<<nwb, B>>>(b2, kk, dd, t00, u00, t, out, n);
}

// round 13
// speedup vs baseline: 1.2768x; 1.2768x over previous
#include <cuda_runtime.h>
#include <math.h>
#include <cstdint>

#define NN 20000
#define EE 320000
#define MMX (EE + NN)
#define FULL 0xffffffffu

// ---------------- scratch ----------------
__device__ float g_z[NN * 512];          // layer-1 aggregated z (pre-divided by sum)
__device__ float g_xa[NN * 128];
__device__ float g_xb[NN * 128];
__device__ float g_s[NN * 4];
__device__ float g_d[NN * 4];
__device__ float g_h2[NN * 3];
__device__ int g_esrc[MMX];
__device__ int g_edst[MMX];
__device__ int g_deg[NN];                // statically zero-initialized; re-zeroed by k_scan
__device__ int g_rowptr[NN + 1];
__device__ int g_cursor[NN];
__device__ int g_csrs[MMX];              // CSR by dst: src node per slot
__device__ float g_A0[16];               // layer0: As(h,i) [0..7], Ad(h,i) [8..15]
__device__ float g_ws[512];              // layer1: w~s_h[k] = W1_h^T as_h
__device__ float g_wd[512];

// ---------------- accurate exp/expm1/elu ----------------
__device__ __forceinline__ float exp_acc(float x) {
    x = fminf(fmaxf(x, -87.0f), 87.0f);
    float kf = rintf(__fmul_rn(x, 1.4426950408889634f));
    float r = __fmaf_rn(kf, -0.69314718246459960938f, x);
    r = __fmaf_rn(kf, 1.9046542743622637e-9f, r);
    float p = 1.9841269841269841e-4f;
    p = __fmaf_rn(p, r, 1.3888888888888889e-3f);
    p = __fmaf_rn(p, r, 8.3333333333333332e-3f);
    p = __fmaf_rn(p, r, 4.1666666666666664e-2f);
    p = __fmaf_rn(p, r, 1.6666666666666666e-1f);
    p = __fmaf_rn(p, r, 0.5f);
    p = __fmaf_rn(p, r, 1.0f);
    p = __fmaf_rn(p, r, 1.0f);
    int ik = (int)kf;
    float s = __int_as_float((ik + 127) << 23);
    return __fmul_rn(p, s);
}
__device__ __forceinline__ float expm1_acc(float x) {
    if (x < -0.34657359f) return __fadd_rn(exp_acc(x), -1.0f);
    float p = 1.9841269841269841e-4f;
    p = __fmaf_rn(p, x, 1.3888888888888889e-3f);
    p = __fmaf_rn(p, x, 8.3333333333333332e-3f);
    p = __fmaf_rn(p, x, 4.1666666666666664e-2f);
    p = __fmaf_rn(p, x, 1.6666666666666666e-1f);
    p = __fmaf_rn(p, x, 0.5f);
    p = __fmaf_rn(p, x, 1.0f);
    return __fmul_rn(p, x);
}
__device__ __forceinline__ float elu_acc(float x) {
    return x > 0.f ? x : expm1_acc(x);
}
__device__ __forceinline__ float lrelu(float x) {
    return x >= 0.f ? x : 0.2f * x;
}
__device__ __forceinline__ float tf32r(float x) {
    float r;
    asm("cvt.rna.tf32.f32 %0, %1;" : "=f"(r) : "f"(x));
    return r;
}

// ---------------- warp mma: m16n8k8 tf32 ----------------
__device__ __forceinline__ void mma_tf32(float* c, const uint32_t* a, const uint32_t* b) {
    asm volatile(
        "mma.sync.aligned.m16n8k8.row.col.f32.tf32.tf32.f32 "
        "{%0,%1,%2,%3}, {%4,%5,%6,%7}, {%8,%9}, {%0,%1,%2,%3};"
        : "+f"(c[0]), "+f"(c[1]), "+f"(c[2]), "+f"(c[3])
        : "r"(a[0]), "r"(a[1]), "r"(a[2]), "r"(a[3]), "r"(b[0]), "r"(b[1]));
}

// ---------------- CSR build ----------------
__global__ void k_edges_count(const int* __restrict__ ei, int e, int m) {
    int i = blockIdx.x * blockDim.x + threadIdx.x;
    if (i >= m) return;
    int s, d;
    if (i < e) { s = ei[i]; d = ei[e + i]; }
    else       { s = i - e; d = i - e; }
    g_esrc[i] = s;
    g_edst[i] = d;
    atomicAdd(&g_deg[d], 1);
}
// Single-block scan; also re-zeroes g_deg for the next replay (graph capture safe:
// static init covers the first call, scan re-zeroes after consuming).
__global__ void k_scan(int n, int m) {
    __shared__ int wsum[32];
    int t = threadIdx.x;
    int lane = t & 31, wid = t >> 5;
    int chunk = (n + 1023) / 1024;
    int b0 = t * chunk;
    int b1 = min(b0 + chunk, n);
    int s = 0;
    for (int i = b0; i < b1; i++) s += g_deg[i];
    int v = s;
#pragma unroll
    for (int o = 1; o < 32; o <<= 1) {
        int u = __shfl_up_sync(FULL, v, o);
        if (lane >= o) v += u;
    }
    if (lane == 31) wsum[wid] = v;
    __syncthreads();
    if (wid == 0) {
        int w = wsum[lane];
#pragma unroll
        for (int o = 1; o < 32; o <<= 1) {
            int u = __shfl_up_sync(FULL, w, o);
            if (lane >= o) w += u;
        }
        wsum[lane] = w;
    }
    __syncthreads();
    int run = (v - s) + (wid > 0 ? wsum[wid - 1] : 0);
    for (int i = b0; i < b1; i++) {
        g_rowptr[i] = run;
        g_cursor[i] = run;
        run += g_deg[i];
        g_deg[i] = 0;     // reset for next replay
    }
    if (t == 0) g_rowptr[n] = m;
}
__global__ void k_fill(int m) {
    int i = blockIdx.x * blockDim.x + threadIdx.x;
    if (i < m) {
        int pos = atomicAdd(&g_cursor[g_edst[i]], 1);
        g_csrs[pos] = g_esrc[i];
    }
}

// ---------------- precompute projected attention vectors ----------------
__global__ void k_pre(const float* __restrict__ W0, const float* __restrict__ as0,
                      const float* __restrict__ ad0,
                      const float* __restrict__ W1, const float* __restrict__ as1,
                      const float* __restrict__ ad1) {
    int t = threadIdx.x;
    if (t < 512) {
        int h = t >> 7, k = t & 127;
        float acc = 0.f;
        for (int c = 0; c < 128; c++)
            acc = __fmaf_rn(as1[h * 128 + c], W1[(size_t)(h * 128 + c) * 128 + k], acc);
        g_ws[t] = acc;
    } else {
        int u = t - 512;
        int h = u >> 7, k = u & 127;
        float acc = 0.f;
        for (int c = 0; c < 128; c++)
            acc = __fmaf_rn(ad1[h * 128 + c], W1[(size_t)(h * 128 + c) * 128 + k], acc);
        g_wd[u] = acc;
    }
    if (t < 16) {
        int h = t & 3, i = (t >> 2) & 1;
        const float* a = (t < 8) ? as0 : ad0;
        float acc = 0.f;
        for (int c = 0; c < 128; c++)
            acc = __fmaf_rn(a[h * 128 + c], W0[(h * 128 + c) * 2 + i], acc);
        g_A0[(t < 8 ? 0 : 8) + h * 2 + i] = acc;
    }
}

// ---------------- layer 0 scores ----------------
__global__ void k_score0(const float* __restrict__ x, int n) {
    int v = blockIdx.x * blockDim.x + threadIdx.x;
    if (v >= n) return;
    float x0 = x[2 * v], x1 = x[2 * v + 1];
    float4 s, d;
    s.x = __fmaf_rn(x0, g_A0[0], x1 * g_A0[1]);
    s.y = __fmaf_rn(x0, g_A0[2], x1 * g_A0[3]);
    s.z = __fmaf_rn(x0, g_A0[4], x1 * g_A0[5]);
    s.w = __fmaf_rn(x0, g_A0[6], x1 * g_A0[7]);
    d.x = __fmaf_rn(x0, g_A0[8],  x1 * g_A0[9]);
    d.y = __fmaf_rn(x0, g_A0[10], x1 * g_A0[11]);
    d.z = __fmaf_rn(x0, g_A0[12], x1 * g_A0[13]);
    d.w = __fmaf_rn(x0, g_A0[14], x1 * g_A0[15]);
    *(float4*)&g_s[v * 4] = s;
    *(float4*)&g_d[v * 4] = d;
}

// ---------------- layer 0: single-pass softmax (no max shift) + rank-2 aggregate + finalize
__global__ void k_l0agg(const float* __restrict__ x, const float* __restrict__ W0,
                        const float* __restrict__ bias,
                        const float* __restrict__ bng, const float* __restrict__ bnb,
                        const float* __restrict__ bnm, const float* __restrict__ bnv, int n) {
    int v = (blockIdx.x * blockDim.x + threadIdx.x) >> 5;
    int lane = threadIdx.x & 31;
    if (v >= n) return;
    int beg = g_rowptr[v], end = g_rowptr[v + 1];
    float4 dv = *(const float4*)&g_d[v * 4];

    float s0 = 0.f, s1 = 0.f, s2 = 0.f, s3 = 0.f;
    float zx0 = 0.f, zx1 = 0.f, zx2 = 0.f, zx3 = 0.f;
    float zy0 = 0.f, zy1 = 0.f, zy2 = 0.f, zy3 = 0.f;
    for (int idx = beg + lane; idx < end; idx += 32) {
        int s = g_csrs[idx];
        float4 sv = *(const float4*)&g_s[s * 4];
        float p0 = exp_acc(lrelu(sv.x + dv.x));
        float p1 = exp_acc(lrelu(sv.y + dv.y));
        float p2 = exp_acc(lrelu(sv.z + dv.z));
        float p3 = exp_acc(lrelu(sv.w + dv.w));
        s0 += p0; s1 += p1; s2 += p2; s3 += p3;
        float2 xv = *(const float2*)&x[2 * s];
        zx0 = __fmaf_rn(p0, xv.x, zx0); zy0 = __fmaf_rn(p0, xv.y, zy0);
        zx1 = __fmaf_rn(p1, xv.x, zx1); zy1 = __fmaf_rn(p1, xv.y, zy1);
        zx2 = __fmaf_rn(p2, xv.x, zx2); zy2 = __fmaf_rn(p2, xv.y, zy2);
        zx3 = __fmaf_rn(p3, xv.x, zx3); zy3 = __fmaf_rn(p3, xv.y, zy3);
    }
#pragma unroll
    for (int o = 16; o > 0; o >>= 1) {
        s0 += __shfl_xor_sync(FULL, s0, o);  s1 += __shfl_xor_sync(FULL, s1, o);
        s2 += __shfl_xor_sync(FULL, s2, o);  s3 += __shfl_xor_sync(FULL, s3, o);
        zx0 += __shfl_xor_sync(FULL, zx0, o); zx1 += __shfl_xor_sync(FULL, zx1, o);
        zx2 += __shfl_xor_sync(FULL, zx2, o); zx3 += __shfl_xor_sync(FULL, zx3, o);
        zy0 += __shfl_xor_sync(FULL, zy0, o); zy1 += __shfl_xor_sync(FULL, zy1, o);
        zy2 += __shfl_xor_sync(FULL, zy2, o); zy3 += __shfl_xor_sync(FULL, zy3, o);
    }
    float d0 = __fadd_rn(s0, 1e-16f);
    float d1 = __fadd_rn(s1, 1e-16f);
    float d2 = __fadd_rn(s2, 1e-16f);
    float d3 = __fadd_rn(s3, 1e-16f);
    float ZX[4] = {zx0, zx1, zx2, zx3};
    float ZY[4] = {zy0, zy1, zy2, zy3};
    float DD[4] = {d0, d1, d2, d3};

    int c = lane * 4;
    float vals[4];
#pragma unroll
    for (int j = 0; j < 4; j++) {
        int cc = c + j;
        float a = 0.f;
#pragma unroll
        for (int h = 0; h < 4; h++) {
            float w0 = W0[(h * 128 + cc) * 2];
            float w1 = W0[(h * 128 + cc) * 2 + 1];
            float tmp = __fmaf_rn(w0, ZX[h], __fmul_rn(w1, ZY[h]));
            a = __fadd_rn(a, __fdiv_rn(tmp, DD[h]));
        }
        float val = __fmul_rn(a, 0.25f);
        val = __fadd_rn(val, bias[cc]);
        val = elu_acc(val);
        float inv = __frsqrt_rn(__fadd_rn(bnv[cc], 1e-5f));
        val = __fadd_rn(__fmul_rn(__fmul_rn(__fsub_rn(val, bnm[cc]), inv), bng[cc]), bnb[cc]);
        vals[j] = val;
    }
    *(float4*)&g_xa[(size_t)v * 128 + c] = make_float4(vals[0], vals[1], vals[2], vals[3]);
}

// ---------------- layer 1 scores ----------------
__global__ void k_score1(int n) {
    int v = (blockIdx.x * blockDim.x + threadIdx.x) >> 5;
    int lane = threadIdx.x & 31;
    if (v >= n) return;
    float4 xv = *(const float4*)&g_xa[(size_t)v * 128 + lane * 4];
    float sp[4], dp[4];
#pragma unroll
    for (int hd = 0; hd < 4; hd++) {
        float4 wv = *(const float4*)&g_ws[hd * 128 + lane * 4];
        float4 uv = *(const float4*)&g_wd[hd * 128 + lane * 4];
        float s = xv.x * wv.x + xv.y * wv.y + xv.z * wv.z + xv.w * wv.w;
        float d = xv.x * uv.x + xv.y * uv.y + xv.z * uv.z + xv.w * uv.w;
#pragma unroll
        for (int o = 16; o > 0; o >>= 1) {
            s += __shfl_xor_sync(FULL, s, o);
            d += __shfl_xor_sync(FULL, d, o);
        }
        sp[hd] = s;
        dp[hd] = d;
    }
    if (lane == 0) {
        *(float4*)&g_s[v * 4] = make_float4(sp[0], sp[1], sp[2], sp[3]);
        *(float4*)&g_d[v * 4] = make_float4(dp[0], dp[1], dp[2], dp[3]);
    }
}

// ---------------- layer 1: single-pass softmax + z-aggregate ----------------
__global__ void k_agg1(int n) {
    int v = (blockIdx.x * blockDim.x + threadIdx.x) >> 5;
    int lane = threadIdx.x & 31;
    if (v >= n) return;
    int beg = g_rowptr[v], end = g_rowptr[v + 1];
    float4 dv = *(const float4*)&g_d[v * 4];

    float acc[16];
#pragma unroll
    for (int i = 0; i < 16; i++) acc[i] = 0.f;
    float s0 = 0.f, s1 = 0.f, s2 = 0.f, s3 = 0.f;

    for (int base = beg; base < end; base += 32) {
        int idx = base + lane;
        int sv = 0;
        float p0 = 0.f, p1 = 0.f, p2 = 0.f, p3 = 0.f;
        if (idx < end) {
            sv = g_csrs[idx];
            float4 ss = *(const float4*)&g_s[sv * 4];
            p0 = exp_acc(lrelu(ss.x + dv.x));
            p1 = exp_acc(lrelu(ss.y + dv.y));
            p2 = exp_acc(lrelu(ss.z + dv.z));
            p3 = exp_acc(lrelu(ss.w + dv.w));
            s0 += p0; s1 += p1; s2 += p2; s3 += p3;
        }
        int cnt = min(32, end - base);
        for (int t = 0; t < cnt; t++) {
            int s = __shfl_sync(FULL, sv, t);
            float q0 = __shfl_sync(FULL, p0, t);
            float q1 = __shfl_sync(FULL, p1, t);
            float q2 = __shfl_sync(FULL, p2, t);
            float q3 = __shfl_sync(FULL, p3, t);
            float4 xv = *(const float4*)&g_xa[(size_t)s * 128 + lane * 4];
            acc[0]  = __fmaf_rn(q0, xv.x, acc[0]);  acc[1]  = __fmaf_rn(q0, xv.y, acc[1]);
            acc[2]  = __fmaf_rn(q0, xv.z, acc[2]);  acc[3]  = __fmaf_rn(q0, xv.w, acc[3]);
            acc[4]  = __fmaf_rn(q1, xv.x, acc[4]);  acc[5]  = __fmaf_rn(q1, xv.y, acc[5]);
            acc[6]  = __fmaf_rn(q1, xv.z, acc[6]);  acc[7]  = __fmaf_rn(q1, xv.w, acc[7]);
            acc[8]  = __fmaf_rn(q2, xv.x, acc[8]);  acc[9]  = __fmaf_rn(q2, xv.y, acc[9]);
            acc[10] = __fmaf_rn(q2, xv.z, acc[10]); acc[11] = __fmaf_rn(q2, xv.w, acc[11]);
            acc[12] = __fmaf_rn(q3, xv.x, acc[12]); acc[13] = __fmaf_rn(q3, xv.y, acc[13]);
            acc[14] = __fmaf_rn(q3, xv.z, acc[14]); acc[15] = __fmaf_rn(q3, xv.w, acc[15]);
        }
    }
#pragma unroll
    for (int o = 16; o > 0; o >>= 1) {
        s0 += __shfl_xor_sync(FULL, s0, o);
        s1 += __shfl_xor_sync(FULL, s1, o);
        s2 += __shfl_xor_sync(FULL, s2, o);
        s3 += __shfl_xor_sync(FULL, s3, o);
    }
    float r0 = __fdiv_rn(1.0f, __fadd_rn(s0, 1e-16f));
    float r1 = __fdiv_rn(1.0f, __fadd_rn(s1, 1e-16f));
    float r2 = __fdiv_rn(1.0f, __fadd_rn(s2, 1e-16f));
    float r3 = __fdiv_rn(1.0f, __fadd_rn(s3, 1e-16f));

    float* zp = &g_z[(size_t)v * 512 + lane * 4];
    *(float4*)&zp[0]   = make_float4(acc[0] * r0,  acc[1] * r0,  acc[2] * r0,  acc[3] * r0);
    *(float4*)&zp[128] = make_float4(acc[4] * r1,  acc[5] * r1,  acc[6] * r1,  acc[7] * r1);
    *(float4*)&zp[256] = make_float4(acc[8] * r2,  acc[9] * r2,  acc[10] * r2, acc[11] * r2);
    *(float4*)&zp[384] = make_float4(acc[12] * r3, acc[13] * r3, acc[14] * r3, acc[15] * r3);
}

// ---------------- layer 1: mma.sync TF32 (3xTF32) GEMM + finalize -> xb (R10 verbatim) ----
#define STR 36
#define SM_AH 0
#define SM_AL (128 * STR)
#define SM_BH (2 * 128 * STR)
#define SM_BL (3 * 128 * STR)
#define MMA_SMEM (4 * 128 * STR * 4)

__global__ void k_gemm_mma(const float* __restrict__ W1, const float* __restrict__ bias,
                           const float* __restrict__ bng, const float* __restrict__ bnb,
                           const float* __restrict__ bnm, const float* __restrict__ bnv,
                           int n) {
    extern __shared__ float sm[];
    int tid = threadIdx.x;
    int wid = tid >> 5, lane = tid & 31;
    int warp_m = wid >> 2;          // 0..1  (64 rows each)
    int warp_n = wid & 3;           // 0..3  (32 cols each)
    int grp = lane >> 2;            // 0..7
    int tig = lane & 3;             // 0..3
    int node0 = blockIdx.x * 128;

    float acc[4][4][4];
#pragma unroll
    for (int mf = 0; mf < 4; mf++)
#pragma unroll
        for (int nf = 0; nf < 4; nf++)
#pragma unroll
            for (int q = 0; q < 4; q++) acc[mf][nf][q] = 0.f;

    for (int ck = 0; ck < 16; ck++) {
        for (int i = tid; i < 128 * 8; i += 256) {
            int row = i >> 3;
            int kl = (i & 7) * 4;
            int nd = node0 + row;
            float4 v = make_float4(0.f, 0.f, 0.f, 0.f);
            if (nd < n) v = *(const float4*)&g_z[(size_t)nd * 512 + ck * 32 + kl];
            float4 h4, l4;
            h4.x = tf32r(v.x); h4.y = tf32r(v.y); h4.z = tf32r(v.z); h4.w = tf32r(v.w);
            l4.x = v.x - h4.x; l4.y = v.y - h4.y; l4.z = v.z - h4.z; l4.w = v.w - h4.w;
            *(float4*)&sm[SM_AH + row * STR + kl] = h4;
            *(float4*)&sm[SM_AL + row * STR + kl] = l4;
        }
        {
            int h = ck >> 2, kb = (ck & 3) * 32;
            for (int i = tid; i < 128 * 8; i += 256) {
                int row = i >> 3;
                int kl = (i & 7) * 4;
                float4 v = *(const float4*)&W1[(size_t)(h * 128 + row) * 128 + kb + kl];
                float4 h4, l4;
                h4.x = tf32r(v.x); h4.y = tf32r(v.y); h4.z = tf32r(v.z); h4.w = tf32r(v.w);
                l4.x = v.x - h4.x; l4.y = v.y - h4.y; l4.z = v.z - h4.z; l4.w = v.w - h4.w;
                *(float4*)&sm[SM_BH + row * STR + kl] = h4;
                *(float4*)&sm[SM_BL + row * STR + kl] = l4;
            }
        }
        __syncthreads();

#pragma unroll
        for (int k8 = 0; k8 < 4; k8++) {
            int k0 = k8 * 8;
            uint32_t ah[4][4], al[4][4], bh[4][2], bl[4][2];
#pragma unroll
            for (int mf = 0; mf < 4; mf++) {
                int r0 = warp_m * 64 + mf * 16;
                ah[mf][0] = __float_as_uint(sm[SM_AH + (r0 + grp) * STR + k0 + tig]);
                ah[mf][1] = __float_as_uint(sm[SM_AH + (r0 + grp + 8) * STR + k0 + tig]);
                ah[mf][2] = __float_as_uint(sm[SM_AH + (r0 + grp) * STR + k0 + tig + 4]);
                ah[mf][3] = __float_as_uint(sm[SM_AH + (r0 + grp + 8) * STR + k0 + tig + 4]);
                al[mf][0] = __float_as_uint(sm[SM_AL + (r0 + grp) * STR + k0 + tig]);
                al[mf][1] = __float_as_uint(sm[SM_AL + (r0 + grp + 8) * STR + k0 + tig]);
                al[mf][2] = __float_as_uint(sm[SM_AL + (r0 + grp) * STR + k0 + tig + 4]);
                al[mf][3] = __float_as_uint(sm[SM_AL + (r0 + grp + 8) * STR + k0 + tig + 4]);
            }
#pragma unroll
            for (int nf = 0; nf < 4; nf++) {
                int c0 = warp_n * 32 + nf * 8;
                bh[nf][0] = __float_as_uint(sm[SM_BH + (c0 + grp) * STR + k0 + tig]);
                bh[nf][1] = __float_as_uint(sm[SM_BH + (c0 + grp) * STR + k0 + tig + 4]);
                bl[nf][0] = __float_as_uint(sm[SM_BL + (c0 + grp) * STR + k0 + tig]);
                bl[nf][1] = __float_as_uint(sm[SM_BL + (c0 + grp) * STR + k0 + tig + 4]);
            }
#pragma unroll
            for (int mf = 0; mf < 4; mf++)
#pragma unroll
                for (int nf = 0; nf < 4; nf++) {
                    mma_tf32(acc[mf][nf], ah[mf], bh[nf]);
                    mma_tf32(acc[mf][nf], ah[mf], bl[nf]);
                    mma_tf32(acc[mf][nf], al[mf], bh[nf]);
                }
        }
        __syncthreads();
    }

#pragma unroll
    for (int mf = 0; mf < 4; mf++) {
        int r0 = node0 + warp_m * 64 + mf * 16 + grp;
#pragma unroll
        for (int half = 0; half < 2; half++) {
            int nd = r0 + half * 8;
            if (nd >= n) continue;
#pragma unroll
            for (int nf = 0; nf < 4; nf++) {
                int c0 = warp_n * 32 + nf * 8 + tig * 2;
                float vv[2];
#pragma unroll
                for (int q = 0; q < 2; q++) {
                    int c = c0 + q;
                    float val = __fmul_rn(acc[mf][nf][half * 2 + q], 0.25f);
                    val = __fadd_rn(val, bias[c]);
                    val = elu_acc(val);
                    float inv = __frsqrt_rn(__fadd_rn(bnv[c], 1e-5f));
                    val = __fadd_rn(__fmul_rn(__fmul_rn(__fsub_rn(val, bnm[c]), inv), bng[c]), bnb[c]);
                    vv[q] = val;
                }
                *(float2*)&g_xb[(size_t)nd * 128 + c0] = make_float2(vv[0], vv[1]);
            }
        }
    }
}

// ---------------- layer 2: fused h2 + scores ----------------
__global__ void k_l2(const float* __restrict__ W, const float* __restrict__ as_,
                     const float* __restrict__ ad_, int n) {
    int v = (blockIdx.x * blockDim.x + threadIdx.x) >> 5;
    int lane = threadIdx.x & 31;
    if (v >= n) return;
    float4 xv = *(const float4*)&g_xb[(size_t)v * 128 + lane * 4];
    float p[3];
#pragma unroll
    for (int o = 0; o < 3; o++) {
        float4 wv = *(const float4*)&W[o * 128 + lane * 4];
        float pp = __fmaf_rn(xv.x, wv.x, __fmaf_rn(xv.y, wv.y, __fmaf_rn(xv.z, wv.z, xv.w * wv.w)));
#pragma unroll
        for (int off = 16; off > 0; off >>= 1) pp += __shfl_xor_sync(FULL, pp, off);
        p[o] = pp;
    }
    if (lane == 0) {
        g_h2[v * 3 + 0] = p[0];
        g_h2[v * 3 + 1] = p[1];
        g_h2[v * 3 + 2] = p[2];
        g_s[v] = __fmaf_rn(p[0], as_[0], __fmaf_rn(p[1], as_[1], p[2] * as_[2]));
        g_d[v] = __fmaf_rn(p[0], ad_[0], __fmaf_rn(p[1], ad_[1], p[2] * ad_[2]));
    }
}

// ---------------- layer 2: single-pass softmax + aggregate + ODE epilogue ----------------
__global__ void k_smax2epi(const float* __restrict__ b2,
                           const float* __restrict__ kk, const float* __restrict__ dd,
                           const float* __restrict__ t00, const float* __restrict__ u00,
                           const float* __restrict__ t, float* __restrict__ out, int n) {
    int v = (blockIdx.x * blockDim.x + threadIdx.x) >> 5;
    int lane = threadIdx.x & 31;
    if (v >= n) return;
    int beg = g_rowptr[v], end = g_rowptr[v + 1];
    float sd = g_d[v];

    float sum = 0.f, a0 = 0.f, a1 = 0.f, a2 = 0.f;
    for (int idx = beg + lane; idx < end; idx += 32) {
        int s = g_csrs[idx];
        float p = exp_acc(lrelu(g_s[s] + sd));
        sum += p;
        a0 = __fmaf_rn(p, g_h2[s * 3 + 0], a0);
        a1 = __fmaf_rn(p, g_h2[s * 3 + 1], a1);
        a2 = __fmaf_rn(p, g_h2[s * 3 + 2], a2);
    }
#pragma unroll
    for (int o = 16; o > 0; o >>= 1) {
        sum += __shfl_xor_sync(FULL, sum, o);
        a0 += __shfl_xor_sync(FULL, a0, o);
        a1 += __shfl_xor_sync(FULL, a1, o);
        a2 += __shfl_xor_sync(FULL, a2, o);
    }
    if (lane == 0) {
        float denom = __fadd_rn(sum, 1e-16f);
        float ar  = elu_acc(__fadd_rn(__fdiv_rn(a0, denom), b2[0]));
        float gam = elu_acc(__fadd_rn(__fdiv_rn(a1, denom), b2[1]));
        float bet = elu_acc(__fadd_rn(__fdiv_rn(a2, denom), b2[2]));

        float tt = t[v];
        float K = kk[0], D = dd[0], T0 = t00[0], U0 = u00[0];

        float z = __fmul_rn(K, __fsub_rn(__fsub_rn(tt, T0), D));
        float S = __fdiv_rn(1.0f, __fadd_rn(1.0f, exp_acc(-z)));
        float oneMS = __fsub_rn(1.0f, S);

        float eb  = exp_acc(__fmul_rn(-bet, tt));
        float eg  = exp_acc(__fmul_rn(-gam, tt));
        float tmt0 = __fsub_rn(tt, T0);
        float ebs = exp_acc(__fmul_rn(-bet, tmt0));
        float egs = exp_acc(__fmul_rn(-gam, tmt0));
        float ab = __fdiv_rn(ar, bet);
        float ag = __fdiv_rn(ar, gam);

        float tu = __fadd_rn(
                     __fadd_rn(__fmul_rn(__fmul_rn(ab, __fsub_rn(1.0f, eb)), oneMS),
                               __fmul_rn(ab, S)),
                     __fmul_rn(__fsub_rn(__fmul_rn(U0, ebs), ab), S));

        float gmb = __fsub_rn(gam, bet);
        float term1 = __fadd_rn(__fmul_rn(ag, __fsub_rn(1.0f, eg)),
                                __fmul_rn(__fdiv_rn(ar, gmb), __fsub_rn(eg, eb)));
        float term3 = __fmul_rn(__fmul_rn(__fdiv_rn(__fmul_rn(bet, U0), gmb),
                                          __fsub_rn(egs, ebs)), S);
        float ts = __fadd_rn(__fadd_rn(__fmul_rn(term1, oneMS), __fmul_rn(ag, S)), term3);

        out[v] = tu;
        out[n + v] = ts;
    }
}

// ---------------- launch ----------------
extern "C" void kernel_launch(void* const* d_in, const int* in_sizes, int n_in,
                              void* d_out, int out_size) {
    int off = (n_in >= 28) ? 0 : -1;
    const float* x    = (const float*)d_in[0];
    const int*   ei   = (const int*)d_in[1];
    const float* W0   = (const float*)d_in[3 + off];
    const float* as0  = (const float*)d_in[4 + off];
    const float* ad0  = (const float*)d_in[5 + off];
    const float* b0   = (const float*)d_in[6 + off];
    const float* W1   = (const float*)d_in[7 + off];
    const float* as1  = (const float*)d_in[8 + off];
    const float* ad1  = (const float*)d_in[9 + off];
    const float* b1   = (const float*)d_in[10 + off];
    const float* W2   = (const float*)d_in[11 + off];
    const float* as2  = (const float*)d_in[12 + off];
    const float* ad2  = (const float*)d_in[13 + off];
    const float* b2   = (const float*)d_in[14 + off];
    const float* bng0 = (const float*)d_in[15 + off];
    const float* bnb0 = (const float*)d_in[16 + off];
    const float* bnm0 = (const float*)d_in[17 + off];
    const float* bnv0 = (const float*)d_in[18 + off];
    const float* bng1 = (const float*)d_in[19 + off];
    const float* bnb1 = (const float*)d_in[20 + off];
    const float* bnm1 = (const float*)d_in[21 + off];
    const float* bnv1 = (const float*)d_in[22 + off];
    const float* kk   = (const float*)d_in[23 + off];
    const float* dd   = (const float*)d_in[24 + off];
    const float* t00  = (const float*)d_in[25 + off];
    const float* u00  = (const float*)d_in[26 + off];
    const float* t    = (const float*)d_in[27 + off];
    float* out = (float*)d_out;

    int n = in_sizes[0] / 2;
    int e = in_sizes[1] / 2;
    int m = e + n;

    const int B = 256;
    auto nb = [](long long x_, int b) { return (int)((x_ + b - 1) / b); };
    int nwb = nb((long long)n * 32, B);   // warp-per-node grids

    cudaFuncSetAttribute(k_gemm_mma, cudaFuncAttributeMaxDynamicSharedMemorySize, MMA_SMEM);

    // CSR build + attention-vector precompute (g_deg re-zeroed inside k_scan)
    k_edges_count<<<nb(m, B), B>>>(ei, e, m);
    k_scan<<<1, 1024>>>(n, m);
    k_fill<<<nb(m, B), B>>>(m);
    k_pre<<<1, 1024>>>(W0, as0, ad0, W1, as1, ad1);

    // ---- layer 0 (h never materialized) ----
    k_score0<<<nb(n, B), B>>>(x, n);
    k_l0agg<<<nwb, B>>>(x, W0, b0, bng0, bnb0, bnm0, bnv0, n);

    // ---- layer 1 (aggregate z first, project after on tensor cores) ----
    k_score1<<<nwb, B>>>(n);
    k_agg1<<<nwb, B>>>(n);
    k_gemm_mma<<<nb(n, 128), 256, MMA_SMEM>>>(W1, b1, bng1, bnb1, bnm1, bnv1, n);

    // ---- layer 2 + epilogue ----
    k_l2<<<nwb, B>>>(W2, as2, ad2, n);
    k_smax2epi<<<nwb, B>>>(b2, kk, dd, t00, u00, t, out, n);
}

// round 14
// speedup vs baseline: 1.3037x; 1.0211x over previous
#include <cuda_runtime.h>
#include <math.h>
#include <cstdint>

#define NN 20000
#define EE 320000
#define MMX (EE + NN)
#define FULL 0xffffffffu

// ---------------- scratch ----------------
__device__ float g_z[NN * 512];          // layer-1 aggregated z (pre-divided by sum)
__device__ float g_xa[NN * 128];
__device__ float g_xb[NN * 128];
__device__ float g_s[NN * 4];
__device__ float g_d[NN * 4];
__device__ float g_h2[NN * 3];
__device__ int g_esrc[MMX];
__device__ int g_edst[MMX];
__device__ int g_deg[NN];                // statically zero-initialized; re-zeroed by k_scan
__device__ int g_rowptr[NN + 1];
__device__ int g_cursor[NN];
__device__ int g_csrs[MMX];              // CSR by dst: src node per slot
__device__ float g_A0[16];               // layer0: As(h,i) [0..7], Ad(h,i) [8..15]
__device__ float g_ws[512];              // layer1: w~s_h[k] = W1_h^T as_h
__device__ float g_wd[512];

// ---------------- accurate exp/expm1/elu ----------------
__device__ __forceinline__ float exp_acc(float x) {
    x = fminf(fmaxf(x, -87.0f), 87.0f);
    float kf = rintf(__fmul_rn(x, 1.4426950408889634f));
    float r = __fmaf_rn(kf, -0.69314718246459960938f, x);
    r = __fmaf_rn(kf, 1.9046542743622637e-9f, r);
    float p = 1.9841269841269841e-4f;
    p = __fmaf_rn(p, r, 1.3888888888888889e-3f);
    p = __fmaf_rn(p, r, 8.3333333333333332e-3f);
    p = __fmaf_rn(p, r, 4.1666666666666664e-2f);
    p = __fmaf_rn(p, r, 1.6666666666666666e-1f);
    p = __fmaf_rn(p, r, 0.5f);
    p = __fmaf_rn(p, r, 1.0f);
    p = __fmaf_rn(p, r, 1.0f);
    int ik = (int)kf;
    float s = __int_as_float((ik + 127) << 23);
    return __fmul_rn(p, s);
}
__device__ __forceinline__ float expm1_acc(float x) {
    if (x < -0.34657359f) return __fadd_rn(exp_acc(x), -1.0f);
    float p = 1.9841269841269841e-4f;
    p = __fmaf_rn(p, x, 1.3888888888888889e-3f);
    p = __fmaf_rn(p, x, 8.3333333333333332e-3f);
    p = __fmaf_rn(p, x, 4.1666666666666664e-2f);
    p = __fmaf_rn(p, x, 1.6666666666666666e-1f);
    p = __fmaf_rn(p, x, 0.5f);
    p = __fmaf_rn(p, x, 1.0f);
    return __fmul_rn(p, x);
}
__device__ __forceinline__ float elu_acc(float x) {
    return x > 0.f ? x : expm1_acc(x);
}
__device__ __forceinline__ float lrelu(float x) {
    return x >= 0.f ? x : 0.2f * x;
}
__device__ __forceinline__ float tf32r(float x) {
    float r;
    asm("cvt.rna.tf32.f32 %0, %1;" : "=f"(r) : "f"(x));
    return r;
}

// ---------------- warp mma: m16n8k8 tf32 ----------------
__device__ __forceinline__ void mma_tf32(float* c, const uint32_t* a, const uint32_t* b) {
    asm volatile(
        "mma.sync.aligned.m16n8k8.row.col.f32.tf32.tf32.f32 "
        "{%0,%1,%2,%3}, {%4,%5,%6,%7}, {%8,%9}, {%0,%1,%2,%3};"
        : "+f"(c[0]), "+f"(c[1]), "+f"(c[2]), "+f"(c[3])
        : "r"(a[0]), "r"(a[1]), "r"(a[2]), "r"(a[3]), "r"(b[0]), "r"(b[1]));
}

// ---------------- CSR build ----------------
__global__ void k_edges_count(const int* __restrict__ ei, int e, int m) {
    int i = blockIdx.x * blockDim.x + threadIdx.x;
    if (i >= m) return;
    int s, d;
    if (i < e) { s = ei[i]; d = ei[e + i]; }
    else       { s = i - e; d = i - e; }
    g_esrc[i] = s;
    g_edst[i] = d;
    atomicAdd(&g_deg[d], 1);
}
// Single-block scan; also re-zeroes g_deg for the next replay.
__global__ void k_scan(int n, int m) {
    __shared__ int wsum[32];
    int t = threadIdx.x;
    int lane = t & 31, wid = t >> 5;
    int chunk = (n + 1023) / 1024;
    int b0 = t * chunk;
    int b1 = min(b0 + chunk, n);
    int s = 0;
    for (int i = b0; i < b1; i++) s += g_deg[i];
    int v = s;
#pragma unroll
    for (int o = 1; o < 32; o <<= 1) {
        int u = __shfl_up_sync(FULL, v, o);
        if (lane >= o) v += u;
    }
    if (lane == 31) wsum[wid] = v;
    __syncthreads();
    if (wid == 0) {
        int w = wsum[lane];
#pragma unroll
        for (int o = 1; o < 32; o <<= 1) {
            int u = __shfl_up_sync(FULL, w, o);
            if (lane >= o) w += u;
        }
        wsum[lane] = w;
    }
    __syncthreads();
    int run = (v - s) + (wid > 0 ? wsum[wid - 1] : 0);
    for (int i = b0; i < b1; i++) {
        g_rowptr[i] = run;
        g_cursor[i] = run;
        run += g_deg[i];
        g_deg[i] = 0;     // reset for next replay
    }
    if (t == 0) g_rowptr[n] = m;
}
__global__ void k_fill(int m) {
    int i = blockIdx.x * blockDim.x + threadIdx.x;
    if (i < m) {
        int pos = atomicAdd(&g_cursor[g_edst[i]], 1);
        g_csrs[pos] = g_esrc[i];
    }
}

// ---------------- parallel precompute of projected attention vectors ----------------
// warp-per-output: warps 0..511 -> g_ws, 512..1023 -> g_wd, 1024..1039 -> g_A0
__global__ void k_pre(const float* __restrict__ W0, const float* __restrict__ as0,
                      const float* __restrict__ ad0,
                      const float* __restrict__ W1, const float* __restrict__ as1,
                      const float* __restrict__ ad1) {
    int w = (blockIdx.x * blockDim.x + threadIdx.x) >> 5;
    int lane = threadIdx.x & 31;
    if (w < 1024) {
        int o = w & 511;
        int h = o >> 7, k = o & 127;
        const float* a = (w < 512) ? as1 : ad1;
        float acc = 0.f;
#pragma unroll
        for (int i = 0; i < 4; i++) {
            int c = lane + i * 32;
            acc = __fmaf_rn(a[h * 128 + c], W1[(size_t)(h * 128 + c) * 128 + k], acc);
        }
#pragma unroll
        for (int o2 = 16; o2 > 0; o2 >>= 1) acc += __shfl_xor_sync(FULL, acc, o2);
        if (lane == 0) {
            if (w < 512) g_ws[o] = acc;
            else g_wd[o] = acc;
        }
    } else if (w < 1040) {
        int t = w - 1024;           // 0..15
        int h = t & 3, i = (t >> 2) & 1;
        const float* a = (t < 8) ? as0 : ad0;
        float acc = 0.f;
#pragma unroll
        for (int j = 0; j < 4; j++) {
            int c = lane + j * 32;
            acc = __fmaf_rn(a[h * 128 + c], W0[(h * 128 + c) * 2 + i], acc);
        }
#pragma unroll
        for (int o2 = 16; o2 > 0; o2 >>= 1) acc += __shfl_xor_sync(FULL, acc, o2);
        if (lane == 0) g_A0[(t < 8 ? 0 : 8) + h * 2 + i] = acc;
    }
}

// ---------------- layer 0 scores ----------------
__global__ void k_score0(const float* __restrict__ x, int n) {
    int v = blockIdx.x * blockDim.x + threadIdx.x;
    if (v >= n) return;
    float x0 = x[2 * v], x1 = x[2 * v + 1];
    float4 s, d;
    s.x = __fmaf_rn(x0, g_A0[0], x1 * g_A0[1]);
    s.y = __fmaf_rn(x0, g_A0[2], x1 * g_A0[3]);
    s.z = __fmaf_rn(x0, g_A0[4], x1 * g_A0[5]);
    s.w = __fmaf_rn(x0, g_A0[6], x1 * g_A0[7]);
    d.x = __fmaf_rn(x0, g_A0[8],  x1 * g_A0[9]);
    d.y = __fmaf_rn(x0, g_A0[10], x1 * g_A0[11]);
    d.z = __fmaf_rn(x0, g_A0[12], x1 * g_A0[13]);
    d.w = __fmaf_rn(x0, g_A0[14], x1 * g_A0[15]);
    *(float4*)&g_s[v * 4] = s;
    *(float4*)&g_d[v * 4] = d;
}

// ---------------- layer 0: single-pass softmax + rank-2 aggregate + finalize ----------------
__global__ void k_l0agg(const float* __restrict__ x, const float* __restrict__ W0,
                        const float* __restrict__ bias,
                        const float* __restrict__ bng, const float* __restrict__ bnb,
                        const float* __restrict__ bnm, const float* __restrict__ bnv, int n) {
    int v = (blockIdx.x * blockDim.x + threadIdx.x) >> 5;
    int lane = threadIdx.x & 31;
    if (v >= n) return;
    int beg = g_rowptr[v], end = g_rowptr[v + 1];
    float4 dv = *(const float4*)&g_d[v * 4];

    float s0 = 0.f, s1 = 0.f, s2 = 0.f, s3 = 0.f;
    float zx0 = 0.f, zx1 = 0.f, zx2 = 0.f, zx3 = 0.f;
    float zy0 = 0.f, zy1 = 0.f, zy2 = 0.f, zy3 = 0.f;
    for (int idx = beg + lane; idx < end; idx += 32) {
        int s = g_csrs[idx];
        float4 sv = *(const float4*)&g_s[s * 4];
        float p0 = exp_acc(lrelu(sv.x + dv.x));
        float p1 = exp_acc(lrelu(sv.y + dv.y));
        float p2 = exp_acc(lrelu(sv.z + dv.z));
        float p3 = exp_acc(lrelu(sv.w + dv.w));
        s0 += p0; s1 += p1; s2 += p2; s3 += p3;
        float2 xv = *(const float2*)&x[2 * s];
        zx0 = __fmaf_rn(p0, xv.x, zx0); zy0 = __fmaf_rn(p0, xv.y, zy0);
        zx1 = __fmaf_rn(p1, xv.x, zx1); zy1 = __fmaf_rn(p1, xv.y, zy1);
        zx2 = __fmaf_rn(p2, xv.x, zx2); zy2 = __fmaf_rn(p2, xv.y, zy2);
        zx3 = __fmaf_rn(p3, xv.x, zx3); zy3 = __fmaf_rn(p3, xv.y, zy3);
    }
#pragma unroll
    for (int o = 16; o > 0; o >>= 1) {
        s0 += __shfl_xor_sync(FULL, s0, o);  s1 += __shfl_xor_sync(FULL, s1, o);
        s2 += __shfl_xor_sync(FULL, s2, o);  s3 += __shfl_xor_sync(FULL, s3, o);
        zx0 += __shfl_xor_sync(FULL, zx0, o); zx1 += __shfl_xor_sync(FULL, zx1, o);
        zx2 += __shfl_xor_sync(FULL, zx2, o); zx3 += __shfl_xor_sync(FULL, zx3, o);
        zy0 += __shfl_xor_sync(FULL, zy0, o); zy1 += __shfl_xor_sync(FULL, zy1, o);
        zy2 += __shfl_xor_sync(FULL, zy2, o); zy3 += __shfl_xor_sync(FULL, zy3, o);
    }
    float d0 = __fadd_rn(s0, 1e-16f);
    float d1 = __fadd_rn(s1, 1e-16f);
    float d2 = __fadd_rn(s2, 1e-16f);
    float d3 = __fadd_rn(s3, 1e-16f);
    float ZX[4] = {zx0, zx1, zx2, zx3};
    float ZY[4] = {zy0, zy1, zy2, zy3};
    float DD[4] = {d0, d1, d2, d3};

    int c = lane * 4;
    float vals[4];
#pragma unroll
    for (int j = 0; j < 4; j++) {
        int cc = c + j;
        float a = 0.f;
#pragma unroll
        for (int h = 0; h < 4; h++) {
            float w0 = W0[(h * 128 + cc) * 2];
            float w1 = W0[(h * 128 + cc) * 2 + 1];
            float tmp = __fmaf_rn(w0, ZX[h], __fmul_rn(w1, ZY[h]));
            a = __fadd_rn(a, __fdiv_rn(tmp, DD[h]));
        }
        float val = __fmul_rn(a, 0.25f);
        val = __fadd_rn(val, bias[cc]);
        val = elu_acc(val);
        float inv = __frsqrt_rn(__fadd_rn(bnv[cc], 1e-5f));
        val = __fadd_rn(__fmul_rn(__fmul_rn(__fsub_rn(val, bnm[cc]), inv), bng[cc]), bnb[cc]);
        vals[j] = val;
    }
    *(float4*)&g_xa[(size_t)v * 128 + c] = make_float4(vals[0], vals[1], vals[2], vals[3]);
}

// ---------------- layer 1 scores ----------------
__global__ void k_score1(int n) {
    int v = (blockIdx.x * blockDim.x + threadIdx.x) >> 5;
    int lane = threadIdx.x & 31;
    if (v >= n) return;
    float4 xv = *(const float4*)&g_xa[(size_t)v * 128 + lane * 4];
    float sp[4], dp[4];
#pragma unroll
    for (int hd = 0; hd < 4; hd++) {
        float4 wv = *(const float4*)&g_ws[hd * 128 + lane * 4];
        float4 uv = *(const float4*)&g_wd[hd * 128 + lane * 4];
        float s = xv.x * wv.x + xv.y * wv.y + xv.z * wv.z + xv.w * wv.w;
        float d = xv.x * uv.x + xv.y * uv.y + xv.z * uv.z + xv.w * uv.w;
#pragma unroll
        for (int o = 16; o > 0; o >>= 1) {
            s += __shfl_xor_sync(FULL, s, o);
            d += __shfl_xor_sync(FULL, d, o);
        }
        sp[hd] = s;
        dp[hd] = d;
    }
    if (lane == 0) {
        *(float4*)&g_s[v * 4] = make_float4(sp[0], sp[1], sp[2], sp[3]);
        *(float4*)&g_d[v * 4] = make_float4(dp[0], dp[1], dp[2], dp[3]);
    }
}

// ---------------- layer 1: single-pass softmax + z-aggregate ----------------
__global__ void k_agg1(int n) {
    int v = (blockIdx.x * blockDim.x + threadIdx.x) >> 5;
    int lane = threadIdx.x & 31;
    if (v >= n) return;
    int beg = g_rowptr[v], end = g_rowptr[v + 1];
    float4 dv = *(const float4*)&g_d[v * 4];

    float acc[16];
#pragma unroll
    for (int i = 0; i < 16; i++) acc[i] = 0.f;
    float s0 = 0.f, s1 = 0.f, s2 = 0.f, s3 = 0.f;

    for (int base = beg; base < end; base += 32) {
        int idx = base + lane;
        int sv = 0;
        float p0 = 0.f, p1 = 0.f, p2 = 0.f, p3 = 0.f;
        if (idx < end) {
            sv = g_csrs[idx];
            float4 ss = *(const float4*)&g_s[sv * 4];
            p0 = exp_acc(lrelu(ss.x + dv.x));
            p1 = exp_acc(lrelu(ss.y + dv.y));
            p2 = exp_acc(lrelu(ss.z + dv.z));
            p3 = exp_acc(lrelu(ss.w + dv.w));
            s0 += p0; s1 += p1; s2 += p2; s3 += p3;
        }
        int cnt = min(32, end - base);
        for (int t = 0; t < cnt; t++) {
            int s = __shfl_sync(FULL, sv, t);
            float q0 = __shfl_sync(FULL, p0, t);
            float q1 = __shfl_sync(FULL, p1, t);
            float q2 = __shfl_sync(FULL, p2, t);
            float q3 = __shfl_sync(FULL, p3, t);
            float4 xv = *(const float4*)&g_xa[(size_t)s * 128 + lane * 4];
            acc[0]  = __fmaf_rn(q0, xv.x, acc[0]);  acc[1]  = __fmaf_rn(q0, xv.y, acc[1]);
            acc[2]  = __fmaf_rn(q0, xv.z, acc[2]);  acc[3]  = __fmaf_rn(q0, xv.w, acc[3]);
            acc[4]  = __fmaf_rn(q1, xv.x, acc[4]);  acc[5]  = __fmaf_rn(q1, xv.y, acc[5]);
            acc[6]  = __fmaf_rn(q1, xv.z, acc[6]);  acc[7]  = __fmaf_rn(q1, xv.w, acc[7]);
            acc[8]  = __fmaf_rn(q2, xv.x, acc[8]);  acc[9]  = __fmaf_rn(q2, xv.y, acc[9]);
            acc[10] = __fmaf_rn(q2, xv.z, acc[10]); acc[11] = __fmaf_rn(q2, xv.w, acc[11]);
            acc[12] = __fmaf_rn(q3, xv.x, acc[12]); acc[13] = __fmaf_rn(q3, xv.y, acc[13]);
            acc[14] = __fmaf_rn(q3, xv.z, acc[14]); acc[15] = __fmaf_rn(q3, xv.w, acc[15]);
        }
    }
#pragma unroll
    for (int o = 16; o > 0; o >>= 1) {
        s0 += __shfl_xor_sync(FULL, s0, o);
        s1 += __shfl_xor_sync(FULL, s1, o);
        s2 += __shfl_xor_sync(FULL, s2, o);
        s3 += __shfl_xor_sync(FULL, s3, o);
    }
    float r0 = __fdiv_rn(1.0f, __fadd_rn(s0, 1e-16f));
    float r1 = __fdiv_rn(1.0f, __fadd_rn(s1, 1e-16f));
    float r2 = __fdiv_rn(1.0f, __fadd_rn(s2, 1e-16f));
    float r3 = __fdiv_rn(1.0f, __fadd_rn(s3, 1e-16f));

    float* zp = &g_z[(size_t)v * 512 + lane * 4];
    *(float4*)&zp[0]   = make_float4(acc[0] * r0,  acc[1] * r0,  acc[2] * r0,  acc[3] * r0);
    *(float4*)&zp[128] = make_float4(acc[4] * r1,  acc[5] * r1,  acc[6] * r1,  acc[7] * r1);
    *(float4*)&zp[256] = make_float4(acc[8] * r2,  acc[9] * r2,  acc[10] * r2, acc[11] * r2);
    *(float4*)&zp[384] = make_float4(acc[12] * r3, acc[13] * r3, acc[14] * r3, acc[15] * r3);
}

// ---------------- layer 1: mma.sync TF32 (3xTF32) GEMM + finalize -> xb ----------------
#define STR 36
#define SM_AH 0
#define SM_AL (128 * STR)
#define SM_BH (2 * 128 * STR)
#define SM_BL (3 * 128 * STR)
#define MMA_SMEM (4 * 128 * STR * 4)

__global__ void k_gemm_mma(const float* __restrict__ W1, const float* __restrict__ bias,
                           const float* __restrict__ bng, const float* __restrict__ bnb,
                           const float* __restrict__ bnm, const float* __restrict__ bnv,
                           int n) {
    extern __shared__ float sm[];
    int tid = threadIdx.x;
    int wid = tid >> 5, lane = tid & 31;
    int warp_m = wid >> 2;          // 0..1  (64 rows each)
    int warp_n = wid & 3;           // 0..3  (32 cols each)
    int grp = lane >> 2;            // 0..7
    int tig = lane & 3;             // 0..3
    int node0 = blockIdx.x * 128;

    float acc[4][4][4];
#pragma unroll
    for (int mf = 0; mf < 4; mf++)
#pragma unroll
        for (int nf = 0; nf < 4; nf++)
#pragma unroll
            for (int q = 0; q < 4; q++) acc[mf][nf][q] = 0.f;

    for (int ck = 0; ck < 16; ck++) {
        for (int i = tid; i < 128 * 8; i += 256) {
            int row = i >> 3;
            int kl = (i & 7) * 4;
            int nd = node0 + row;
            float4 v = make_float4(0.f, 0.f, 0.f, 0.f);
            if (nd < n) v = *(const float4*)&g_z[(size_t)nd * 512 + ck * 32 + kl];
            float4 h4, l4;
            h4.x = tf32r(v.x); h4.y = tf32r(v.y); h4.z = tf32r(v.z); h4.w = tf32r(v.w);
            l4.x = v.x - h4.x; l4.y = v.y - h4.y; l4.z = v.z - h4.z; l4.w = v.w - h4.w;
            *(float4*)&sm[SM_AH + row * STR + kl] = h4;
            *(float4*)&sm[SM_AL + row * STR + kl] = l4;
        }
        {
            int h = ck >> 2, kb = (ck & 3) * 32;
            for (int i = tid; i < 128 * 8; i += 256) {
                int row = i >> 3;
                int kl = (i & 7) * 4;
                float4 v = *(const float4*)&W1[(size_t)(h * 128 + row) * 128 + kb + kl];
                float4 h4, l4;
                h4.x = tf32r(v.x); h4.y = tf32r(v.y); h4.z = tf32r(v.z); h4.w = tf32r(v.w);
                l4.x = v.x - h4.x; l4.y = v.y - h4.y; l4.z = v.z - h4.z; l4.w = v.w - h4.w;
                *(float4*)&sm[SM_BH + row * STR + kl] = h4;
                *(float4*)&sm[SM_BL + row * STR + kl] = l4;
            }
        }
        __syncthreads();

#pragma unroll
        for (int k8 = 0; k8 < 4; k8++) {
            int k0 = k8 * 8;
            uint32_t ah[4][4], al[4][4], bh[4][2], bl[4][2];
#pragma unroll
            for (int mf = 0; mf < 4; mf++) {
                int r0 = warp_m * 64 + mf * 16;
                ah[mf][0] = __float_as_uint(sm[SM_AH + (r0 + grp) * STR + k0 + tig]);
                ah[mf][1] = __float_as_uint(sm[SM_AH + (r0 + grp + 8) * STR + k0 + tig]);
                ah[mf][2] = __float_as_uint(sm[SM_AH + (r0 + grp) * STR + k0 + tig + 4]);
                ah[mf][3] = __float_as_uint(sm[SM_AH + (r0 + grp + 8) * STR + k0 + tig + 4]);
                al[mf][0] = __float_as_uint(sm[SM_AL + (r0 + grp) * STR + k0 + tig]);
                al[mf][1] = __float_as_uint(sm[SM_AL + (r0 + grp + 8) * STR + k0 + tig]);
                al[mf][2] = __float_as_uint(sm[SM_AL + (r0 + grp) * STR + k0 + tig + 4]);
                al[mf][3] = __float_as_uint(sm[SM_AL + (r0 + grp + 8) * STR + k0 + tig + 4]);
            }
#pragma unroll
            for (int nf = 0; nf < 4; nf++) {
                int c0 = warp_n * 32 + nf * 8;
                bh[nf][0] = __float_as_uint(sm[SM_BH + (c0 + grp) * STR + k0 + tig]);
                bh[nf][1] = __float_as_uint(sm[SM_BH + (c0 + grp) * STR + k0 + tig + 4]);
                bl[nf][0] = __float_as_uint(sm[SM_BL + (c0 + grp) * STR + k0 + tig]);
                bl[nf][1] = __float_as_uint(sm[SM_BL + (c0 + grp) * STR + k0 + tig + 4]);
            }
#pragma unroll
            for (int mf = 0; mf < 4; mf++)
#pragma unroll
                for (int nf = 0; nf < 4; nf++) {
                    mma_tf32(acc[mf][nf], ah[mf], bh[nf]);
                    mma_tf32(acc[mf][nf], ah[mf], bl[nf]);
                    mma_tf32(acc[mf][nf], al[mf], bh[nf]);
                }
        }
        __syncthreads();
    }

#pragma unroll
    for (int mf = 0; mf < 4; mf++) {
        int r0 = node0 + warp_m * 64 + mf * 16 + grp;
#pragma unroll
        for (int half = 0; half < 2; half++) {
            int nd = r0 + half * 8;
            if (nd >= n) continue;
#pragma unroll
            for (int nf = 0; nf < 4; nf++) {
                int c0 = warp_n * 32 + nf * 8 + tig * 2;
                float vv[2];
#pragma unroll
                for (int q = 0; q < 2; q++) {
                    int c = c0 + q;
                    float val = __fmul_rn(acc[mf][nf][half * 2 + q], 0.25f);
                    val = __fadd_rn(val, bias[c]);
                    val = elu_acc(val);
                    float inv = __frsqrt_rn(__fadd_rn(bnv[c], 1e-5f));
                    val = __fadd_rn(__fmul_rn(__fmul_rn(__fsub_rn(val, bnm[c]), inv), bng[c]), bnb[c]);
                    vv[q] = val;
                }
                *(float2*)&g_xb[(size_t)nd * 128 + c0] = make_float2(vv[0], vv[1]);
            }
        }
    }
}

// ---------------- layer 2: fused h2 + scores ----------------
__global__ void k_l2(const float* __restrict__ W, const float* __restrict__ as_,
                     const float* __restrict__ ad_, int n) {
    int v = (blockIdx.x * blockDim.x + threadIdx.x) >> 5;
    int lane = threadIdx.x & 31;
    if (v >= n) return;
    float4 xv = *(const float4*)&g_xb[(size_t)v * 128 + lane * 4];
    float p[3];
#pragma unroll
    for (int o = 0; o < 3; o++) {
        float4 wv = *(const float4*)&W[o * 128 + lane * 4];
        float pp = __fmaf_rn(xv.x, wv.x, __fmaf_rn(xv.y, wv.y, __fmaf_rn(xv.z, wv.z, xv.w * wv.w)));
#pragma unroll
        for (int off = 16; off > 0; off >>= 1) pp += __shfl_xor_sync(FULL, pp, off);
        p[o] = pp;
    }
    if (lane == 0) {
        g_h2[v * 3 + 0] = p[0];
        g_h2[v * 3 + 1] = p[1];
        g_h2[v * 3 + 2] = p[2];
        g_s[v] = __fmaf_rn(p[0], as_[0], __fmaf_rn(p[1], as_[1], p[2] * as_[2]));
        g_d[v] = __fmaf_rn(p[0], ad_[0], __fmaf_rn(p[1], ad_[1], p[2] * ad_[2]));
    }
}

// ---------------- layer 2: single-pass softmax + aggregate + ODE epilogue ----------------
__global__ void k_smax2epi(const float* __restrict__ b2,
                           const float* __restrict__ kk, const float* __restrict__ dd,
                           const float* __restrict__ t00, const float* __restrict__ u00,
                           const float* __restrict__ t, float* __restrict__ out, int n) {
    int v = (blockIdx.x * blockDim.x + threadIdx.x) >> 5;
    int lane = threadIdx.x & 31;
    if (v >= n) return;
    int beg = g_rowptr[v], end = g_rowptr[v + 1];
    float sd = g_d[v];

    float sum = 0.f, a0 = 0.f, a1 = 0.f, a2 = 0.f;
    for (int idx = beg + lane; idx < end; idx += 32) {
        int s = g_csrs[idx];
        float p = exp_acc(lrelu(g_s[s] + sd));
        sum += p;
        a0 = __fmaf_rn(p, g_h2[s * 3 + 0], a0);
        a1 = __fmaf_rn(p, g_h2[s * 3 + 1], a1);
        a2 = __fmaf_rn(p, g_h2[s * 3 + 2], a2);
    }
#pragma unroll
    for (int o = 16; o > 0; o >>= 1) {
        sum += __shfl_xor_sync(FULL, sum, o);
        a0 += __shfl_xor_sync(FULL, a0, o);
        a1 += __shfl_xor_sync(FULL, a1, o);
        a2 += __shfl_xor_sync(FULL, a2, o);
    }
    if (lane == 0) {
        float denom = __fadd_rn(sum, 1e-16f);
        float ar  = elu_acc(__fadd_rn(__fdiv_rn(a0, denom), b2[0]));
        float gam = elu_acc(__fadd_rn(__fdiv_rn(a1, denom), b2[1]));
        float bet = elu_acc(__fadd_rn(__fdiv_rn(a2, denom), b2[2]));

        float tt = t[v];
        float K = kk[0], D = dd[0], T0 = t00[0], U0 = u00[0];

        float z = __fmul_rn(K, __fsub_rn(__fsub_rn(tt, T0), D));
        float S = __fdiv_rn(1.0f, __fadd_rn(1.0f, exp_acc(-z)));
        float oneMS = __fsub_rn(1.0f, S);

        float eb  = exp_acc(__fmul_rn(-bet, tt));
        float eg  = exp_acc(__fmul_rn(-gam, tt));
        float tmt0 = __fsub_rn(tt, T0);
        float ebs = exp_acc(__fmul_rn(-bet, tmt0));
        float egs = exp_acc(__fmul_rn(-gam, tmt0));
        float ab = __fdiv_rn(ar, bet);
        float ag = __fdiv_rn(ar, gam);

        float tu = __fadd_rn(
                     __fadd_rn(__fmul_rn(__fmul_rn(ab, __fsub_rn(1.0f, eb)), oneMS),
                               __fmul_rn(ab, S)),
                     __fmul_rn(__fsub_rn(__fmul_rn(U0, ebs), ab), S));

        float gmb = __fsub_rn(gam, bet);
        float term1 = __fadd_rn(__fmul_rn(ag, __fsub_rn(1.0f, eg)),
                                __fmul_rn(__fdiv_rn(ar, gmb), __fsub_rn(eg, eb)));
        float term3 = __fmul_rn(__fmul_rn(__fdiv_rn(__fmul_rn(bet, U0), gmb),
                                          __fsub_rn(egs, ebs)), S);
        float ts = __fadd_rn(__fadd_rn(__fmul_rn(term1, oneMS), __fmul_rn(ag, S)), term3);

        out[v] = tu;
        out[n + v] = ts;
    }
}

// ---------------- launch ----------------
extern "C" void kernel_launch(void* const* d_in, const int* in_sizes, int n_in,
                              void* d_out, int out_size) {
    int off = (n_in >= 28) ? 0 : -1;
    const float* x    = (const float*)d_in[0];
    const int*   ei   = (const int*)d_in[1];
    const float* W0   = (const float*)d_in[3 + off];
    const float* as0  = (const float*)d_in[4 + off];
    const float* ad0  = (const float*)d_in[5 + off];
    const float* b0   = (const float*)d_in[6 + off];
    const float* W1   = (const float*)d_in[7 + off];
    const float* as1  = (const float*)d_in[8 + off];
    const float* ad1  = (const float*)d_in[9 + off];
    const float* b1   = (const float*)d_in[10 + off];
    const float* W2   = (const float*)d_in[11 + off];
    const float* as2  = (const float*)d_in[12 + off];
    const float* ad2  = (const float*)d_in[13 + off];
    const float* b2   = (const float*)d_in[14 + off];
    const float* bng0 = (const float*)d_in[15 + off];
    const float* bnb0 = (const float*)d_in[16 + off];
    const float* bnm0 = (const float*)d_in[17 + off];
    const float* bnv0 = (const float*)d_in[18 + off];
    const float* bng1 = (const float*)d_in[19 + off];
    const float* bnb1 = (const float*)d_in[20 + off];
    const float* bnm1 = (const float*)d_in[21 + off];
    const float* bnv1 = (const float*)d_in[22 + off];
    const float* kk   = (const float*)d_in[23 + off];
    const float* dd   = (const float*)d_in[24 + off];
    const float* t00  = (const float*)d_in[25 + off];
    const float* u00  = (const float*)d_in[26 + off];
    const float* t    = (const float*)d_in[27 + off];
    float* out = (float*)d_out;

    int n = in_sizes[0] / 2;
    int e = in_sizes[1] / 2;
    int m = e + n;

    const int B = 256;
    auto nb = [](long long x_, int b) { return (int)((x_ + b - 1) / b); };
    int nwb = nb((long long)n * 32, B);   // warp-per-node grids

    cudaFuncSetAttribute(k_gemm_mma, cudaFuncAttributeMaxDynamicSharedMemorySize, MMA_SMEM);

    // CSR build + attention-vector precompute (parallel, 1040 warps)
    k_edges_count<<<nb(m, B), B>>>(ei, e, m);
    k_scan<<<1, 1024>>>(n, m);
    k_fill<<<nb(m, B), B>>>(m);
    k_pre<<<130, 256>>>(W0, as0, ad0, W1, as1, ad1);

    // ---- layer 0 (h never materialized) ----
    k_score0<<<nb(n, B), B>>>(x, n);
    k_l0agg<<<nwb, B>>>(x, W0, b0, bng0, bnb0, bnm0, bnv0, n);

    // ---- layer 1 (aggregate z first, project after on tensor cores) ----
    k_score1<<<nwb, B>>>(n);
    k_agg1<<<nwb, B>>>(n);
    k_gemm_mma<<<nb(n, 128), 256, MMA_SMEM>>>(W1, b1, bng1, bnb1, bnm1, bnv1, n);

    // ---- layer 2 + epilogue ----
    k_l2<<<nwb, B>>>(W2, as2, ad2, n);
    k_smax2epi<<<nwb, B>>>(b2, kk, dd, t00, u00, t, out, n);
}

// round 15
// speedup vs baseline: 1.3594x; 1.0428x over previous
#include <cuda_runtime.h>
#include <math.h>
#include <cstdint>

#define NN 20000
#define EE 320000
#define MMX (EE + NN)
#define FULL 0xffffffffu

// ---------------- scratch ----------------
__device__ float g_z[NN * 512];          // layer-1 aggregated z (pre-divided by sum)
__device__ float g_xa[NN * 128];
__device__ float g_xb[NN * 128];
__device__ float g_s[NN * 4];
__device__ float g_d[NN * 4];
__device__ float g_h2[NN * 3];
__device__ int g_esrc[MMX];
__device__ int g_edst[MMX];
__device__ int g_deg[NN];                // statically zero-initialized; re-zeroed by k_scan
__device__ int g_rowptr[NN + 1];
__device__ int g_cursor[NN];
__device__ int g_csrs[MMX];              // CSR by dst: src node per slot
__device__ float g_A0[16];               // layer0: As(h,i) [0..7], Ad(h,i) [8..15]
__device__ float g_ws[512];              // layer1: w~s_h[k] = W1_h^T as_h
__device__ float g_wd[512];

// ---------------- accurate exp/expm1/elu ----------------
__device__ __forceinline__ float exp_acc(float x) {
    x = fminf(fmaxf(x, -87.0f), 87.0f);
    float kf = rintf(__fmul_rn(x, 1.4426950408889634f));
    float r = __fmaf_rn(kf, -0.69314718246459960938f, x);
    r = __fmaf_rn(kf, 1.9046542743622637e-9f, r);
    float p = 1.9841269841269841e-4f;
    p = __fmaf_rn(p, r, 1.3888888888888889e-3f);
    p = __fmaf_rn(p, r, 8.3333333333333332e-3f);
    p = __fmaf_rn(p, r, 4.1666666666666664e-2f);
    p = __fmaf_rn(p, r, 1.6666666666666666e-1f);
    p = __fmaf_rn(p, r, 0.5f);
    p = __fmaf_rn(p, r, 1.0f);
    p = __fmaf_rn(p, r, 1.0f);
    int ik = (int)kf;
    float s = __int_as_float((ik + 127) << 23);
    return __fmul_rn(p, s);
}
__device__ __forceinline__ float expm1_acc(float x) {
    if (x < -0.34657359f) return __fadd_rn(exp_acc(x), -1.0f);
    float p = 1.9841269841269841e-4f;
    p = __fmaf_rn(p, x, 1.3888888888888889e-3f);
    p = __fmaf_rn(p, x, 8.3333333333333332e-3f);
    p = __fmaf_rn(p, x, 4.1666666666666664e-2f);
    p = __fmaf_rn(p, x, 1.6666666666666666e-1f);
    p = __fmaf_rn(p, x, 0.5f);
    p = __fmaf_rn(p, x, 1.0f);
    return __fmul_rn(p, x);
}
__device__ __forceinline__ float elu_acc(float x) {
    return x > 0.f ? x : expm1_acc(x);
}
__device__ __forceinline__ float lrelu(float x) {
    return x >= 0.f ? x : 0.2f * x;
}
__device__ __forceinline__ float tf32r(float x) {
    float r;
    asm("cvt.rna.tf32.f32 %0, %1;" : "=f"(r) : "f"(x));
    return r;
}

// ---------------- warp mma: m16n8k8 tf32 ----------------
__device__ __forceinline__ void mma_tf32(float* c, const uint32_t* a, const uint32_t* b) {
    asm volatile(
        "mma.sync.aligned.m16n8k8.row.col.f32.tf32.tf32.f32 "
        "{%0,%1,%2,%3}, {%4,%5,%6,%7}, {%8,%9}, {%0,%1,%2,%3};"
        : "+f"(c[0]), "+f"(c[1]), "+f"(c[2]), "+f"(c[3])
        : "r"(a[0]), "r"(a[1]), "r"(a[2]), "r"(a[3]), "r"(b[0]), "r"(b[1]));
}
__device__ __forceinline__ uint32_t smem_to_u32(const void* p) {
    uint32_t a;
    asm("{ .reg .u64 t; cvta.to.shared.u64 t, %1; cvt.u32.u64 %0, t; }" : "=r"(a) : "l"(p));
    return a;
}
__device__ __forceinline__ void cpasync16(uint32_t dst, const void* src, int srcsize) {
    asm volatile("cp.async.cg.shared.global [%0], [%1], 16, %2;"
                 :: "r"(dst), "l"(src), "r"(srcsize));
}
#define CP_COMMIT() asm volatile("cp.async.commit_group;" ::: "memory")
#define CP_WAIT1() asm volatile("cp.async.wait_group 1;" ::: "memory")
#define CP_WAIT0() asm volatile("cp.async.wait_group 0;" ::: "memory")

// ---------------- CSR build ----------------
__global__ void k_edges_count(const int* __restrict__ ei, int e, int m) {
    int i = blockIdx.x * blockDim.x + threadIdx.x;
    if (i >= m) return;
    int s, d;
    if (i < e) { s = ei[i]; d = ei[e + i]; }
    else       { s = i - e; d = i - e; }
    g_esrc[i] = s;
    g_edst[i] = d;
    atomicAdd(&g_deg[d], 1);
}
// Single-block scan; also re-zeroes g_deg for the next replay.
__global__ void k_scan(int n, int m) {
    __shared__ int wsum[32];
    int t = threadIdx.x;
    int lane = t & 31, wid = t >> 5;
    int chunk = (n + 1023) / 1024;
    int b0 = t * chunk;
    int b1 = min(b0 + chunk, n);
    int s = 0;
    for (int i = b0; i < b1; i++) s += g_deg[i];
    int v = s;
#pragma unroll
    for (int o = 1; o < 32; o <<= 1) {
        int u = __shfl_up_sync(FULL, v, o);
        if (lane >= o) v += u;
    }
    if (lane == 31) wsum[wid] = v;
    __syncthreads();
    if (wid == 0) {
        int w = wsum[lane];
#pragma unroll
        for (int o = 1; o < 32; o <<= 1) {
            int u = __shfl_up_sync(FULL, w, o);
            if (lane >= o) w += u;
        }
        wsum[lane] = w;
    }
    __syncthreads();
    int run = (v - s) + (wid > 0 ? wsum[wid - 1] : 0);
    for (int i = b0; i < b1; i++) {
        g_rowptr[i] = run;
        g_cursor[i] = run;
        run += g_deg[i];
        g_deg[i] = 0;     // reset for next replay
    }
    if (t == 0) g_rowptr[n] = m;
}
__global__ void k_fill(int m) {
    int i = blockIdx.x * blockDim.x + threadIdx.x;
    if (i < m) {
        int pos = atomicAdd(&g_cursor[g_edst[i]], 1);
        g_csrs[pos] = g_esrc[i];
    }
}

// ---------------- parallel precompute of projected attention vectors ----------------
__global__ void k_pre(const float* __restrict__ W0, const float* __restrict__ as0,
                      const float* __restrict__ ad0,
                      const float* __restrict__ W1, const float* __restrict__ as1,
                      const float* __restrict__ ad1) {
    int w = (blockIdx.x * blockDim.x + threadIdx.x) >> 5;
    int lane = threadIdx.x & 31;
    if (w < 1024) {
        int o = w & 511;
        int h = o >> 7, k = o & 127;
        const float* a = (w < 512) ? as1 : ad1;
        float acc = 0.f;
#pragma unroll
        for (int i = 0; i < 4; i++) {
            int c = lane + i * 32;
            acc = __fmaf_rn(a[h * 128 + c], W1[(size_t)(h * 128 + c) * 128 + k], acc);
        }
#pragma unroll
        for (int o2 = 16; o2 > 0; o2 >>= 1) acc += __shfl_xor_sync(FULL, acc, o2);
        if (lane == 0) {
            if (w < 512) g_ws[o] = acc;
            else g_wd[o] = acc;
        }
    } else if (w < 1040) {
        int t = w - 1024;           // 0..15
        int h = t & 3, i = (t >> 2) & 1;
        const float* a = (t < 8) ? as0 : ad0;
        float acc = 0.f;
#pragma unroll
        for (int j = 0; j < 4; j++) {
            int c = lane + j * 32;
            acc = __fmaf_rn(a[h * 128 + c], W0[(h * 128 + c) * 2 + i], acc);
        }
#pragma unroll
        for (int o2 = 16; o2 > 0; o2 >>= 1) acc += __shfl_xor_sync(FULL, acc, o2);
        if (lane == 0) g_A0[(t < 8 ? 0 : 8) + h * 2 + i] = acc;
    }
}

// ---------------- layer 0 scores ----------------
__global__ void k_score0(const float* __restrict__ x, int n) {
    int v = blockIdx.x * blockDim.x + threadIdx.x;
    if (v >= n) return;
    float x0 = x[2 * v], x1 = x[2 * v + 1];
    float4 s, d;
    s.x = __fmaf_rn(x0, g_A0[0], x1 * g_A0[1]);
    s.y = __fmaf_rn(x0, g_A0[2], x1 * g_A0[3]);
    s.z = __fmaf_rn(x0, g_A0[4], x1 * g_A0[5]);
    s.w = __fmaf_rn(x0, g_A0[6], x1 * g_A0[7]);
    d.x = __fmaf_rn(x0, g_A0[8],  x1 * g_A0[9]);
    d.y = __fmaf_rn(x0, g_A0[10], x1 * g_A0[11]);
    d.z = __fmaf_rn(x0, g_A0[12], x1 * g_A0[13]);
    d.w = __fmaf_rn(x0, g_A0[14], x1 * g_A0[15]);
    *(float4*)&g_s[v * 4] = s;
    *(float4*)&g_d[v * 4] = d;
}

// ---------------- layer 0: single-pass softmax + rank-2 aggregate + finalize ----------------
__global__ void k_l0agg(const float* __restrict__ x, const float* __restrict__ W0,
                        const float* __restrict__ bias,
                        const float* __restrict__ bng, const float* __restrict__ bnb,
                        const float* __restrict__ bnm, const float* __restrict__ bnv, int n) {
    int v = (blockIdx.x * blockDim.x + threadIdx.x) >> 5;
    int lane = threadIdx.x & 31;
    if (v >= n) return;
    int beg = g_rowptr[v], end = g_rowptr[v + 1];
    float4 dv = *(const float4*)&g_d[v * 4];

    float s0 = 0.f, s1 = 0.f, s2 = 0.f, s3 = 0.f;
    float zx0 = 0.f, zx1 = 0.f, zx2 = 0.f, zx3 = 0.f;
    float zy0 = 0.f, zy1 = 0.f, zy2 = 0.f, zy3 = 0.f;
    for (int idx = beg + lane; idx < end; idx += 32) {
        int s = g_csrs[idx];
        float4 sv = *(const float4*)&g_s[s * 4];
        float p0 = exp_acc(lrelu(sv.x + dv.x));
        float p1 = exp_acc(lrelu(sv.y + dv.y));
        float p2 = exp_acc(lrelu(sv.z + dv.z));
        float p3 = exp_acc(lrelu(sv.w + dv.w));
        s0 += p0; s1 += p1; s2 += p2; s3 += p3;
        float2 xv = *(const float2*)&x[2 * s];
        zx0 = __fmaf_rn(p0, xv.x, zx0); zy0 = __fmaf_rn(p0, xv.y, zy0);
        zx1 = __fmaf_rn(p1, xv.x, zx1); zy1 = __fmaf_rn(p1, xv.y, zy1);
        zx2 = __fmaf_rn(p2, xv.x, zx2); zy2 = __fmaf_rn(p2, xv.y, zy2);
        zx3 = __fmaf_rn(p3, xv.x, zx3); zy3 = __fmaf_rn(p3, xv.y, zy3);
    }
#pragma unroll
    for (int o = 16; o > 0; o >>= 1) {
        s0 += __shfl_xor_sync(FULL, s0, o);  s1 += __shfl_xor_sync(FULL, s1, o);
        s2 += __shfl_xor_sync(FULL, s2, o);  s3 += __shfl_xor_sync(FULL, s3, o);
        zx0 += __shfl_xor_sync(FULL, zx0, o); zx1 += __shfl_xor_sync(FULL, zx1, o);
        zx2 += __shfl_xor_sync(FULL, zx2, o); zx3 += __shfl_xor_sync(FULL, zx3, o);
        zy0 += __shfl_xor_sync(FULL, zy0, o); zy1 += __shfl_xor_sync(FULL, zy1, o);
        zy2 += __shfl_xor_sync(FULL, zy2, o); zy3 += __shfl_xor_sync(FULL, zy3, o);
    }
    float d0 = __fadd_rn(s0, 1e-16f);
    float d1 = __fadd_rn(s1, 1e-16f);
    float d2 = __fadd_rn(s2, 1e-16f);
    float d3 = __fadd_rn(s3, 1e-16f);
    float ZX[4] = {zx0, zx1, zx2, zx3};
    float ZY[4] = {zy0, zy1, zy2, zy3};
    float DD[4] = {d0, d1, d2, d3};

    int c = lane * 4;
    float vals[4];
#pragma unroll
    for (int j = 0; j < 4; j++) {
        int cc = c + j;
        float a = 0.f;
#pragma unroll
        for (int h = 0; h < 4; h++) {
            float w0 = W0[(h * 128 + cc) * 2];
            float w1 = W0[(h * 128 + cc) * 2 + 1];
            float tmp = __fmaf_rn(w0, ZX[h], __fmul_rn(w1, ZY[h]));
            a = __fadd_rn(a, __fdiv_rn(tmp, DD[h]));
        }
        float val = __fmul_rn(a, 0.25f);
        val = __fadd_rn(val, bias[cc]);
        val = elu_acc(val);
        float inv = __frsqrt_rn(__fadd_rn(bnv[cc], 1e-5f));
        val = __fadd_rn(__fmul_rn(__fmul_rn(__fsub_rn(val, bnm[cc]), inv), bng[cc]), bnb[cc]);
        vals[j] = val;
    }
    *(float4*)&g_xa[(size_t)v * 128 + c] = make_float4(vals[0], vals[1], vals[2], vals[3]);
}

// ---------------- layer 1 scores ----------------
__global__ void k_score1(int n) {
    int v = (blockIdx.x * blockDim.x + threadIdx.x) >> 5;
    int lane = threadIdx.x & 31;
    if (v >= n) return;
    float4 xv = *(const float4*)&g_xa[(size_t)v * 128 + lane * 4];
    float sp[4], dp[4];
#pragma unroll
    for (int hd = 0; hd < 4; hd++) {
        float4 wv = *(const float4*)&g_ws[hd * 128 + lane * 4];
        float4 uv = *(const float4*)&g_wd[hd * 128 + lane * 4];
        float s = xv.x * wv.x + xv.y * wv.y + xv.z * wv.z + xv.w * wv.w;
        float d = xv.x * uv.x + xv.y * uv.y + xv.z * uv.z + xv.w * uv.w;
#pragma unroll
        for (int o = 16; o > 0; o >>= 1) {
            s += __shfl_xor_sync(FULL, s, o);
            d += __shfl_xor_sync(FULL, d, o);
        }
        sp[hd] = s;
        dp[hd] = d;
    }
    if (lane == 0) {
        *(float4*)&g_s[v * 4] = make_float4(sp[0], sp[1], sp[2], sp[3]);
        *(float4*)&g_d[v * 4] = make_float4(dp[0], dp[1], dp[2], dp[3]);
    }
}

// ---------------- layer 1: single-pass softmax + z-aggregate ----------------
__global__ void k_agg1(int n) {
    int v = (blockIdx.x * blockDim.x + threadIdx.x) >> 5;
    int lane = threadIdx.x & 31;
    if (v >= n) return;
    int beg = g_rowptr[v], end = g_rowptr[v + 1];
    float4 dv = *(const float4*)&g_d[v * 4];

    float acc[16];
#pragma unroll
    for (int i = 0; i < 16; i++) acc[i] = 0.f;
    float s0 = 0.f, s1 = 0.f, s2 = 0.f, s3 = 0.f;

    for (int base = beg; base < end; base += 32) {
        int idx = base + lane;
        int sv = 0;
        float p0 = 0.f, p1 = 0.f, p2 = 0.f, p3 = 0.f;
        if (idx < end) {
            sv = g_csrs[idx];
            float4 ss = *(const float4*)&g_s[sv * 4];
            p0 = exp_acc(lrelu(ss.x + dv.x));
            p1 = exp_acc(lrelu(ss.y + dv.y));
            p2 = exp_acc(lrelu(ss.z + dv.z));
            p3 = exp_acc(lrelu(ss.w + dv.w));
            s0 += p0; s1 += p1; s2 += p2; s3 += p3;
        }
        int cnt = min(32, end - base);
        for (int t = 0; t < cnt; t++) {
            int s = __shfl_sync(FULL, sv, t);
            float q0 = __shfl_sync(FULL, p0, t);
            float q1 = __shfl_sync(FULL, p1, t);
            float q2 = __shfl_sync(FULL, p2, t);
            float q3 = __shfl_sync(FULL, p3, t);
            float4 xv = *(const float4*)&g_xa[(size_t)s * 128 + lane * 4];
            acc[0]  = __fmaf_rn(q0, xv.x, acc[0]);  acc[1]  = __fmaf_rn(q0, xv.y, acc[1]);
            acc[2]  = __fmaf_rn(q0, xv.z, acc[2]);  acc[3]  = __fmaf_rn(q0, xv.w, acc[3]);
            acc[4]  = __fmaf_rn(q1, xv.x, acc[4]);  acc[5]  = __fmaf_rn(q1, xv.y, acc[5]);
            acc[6]  = __fmaf_rn(q1, xv.z, acc[6]);  acc[7]  = __fmaf_rn(q1, xv.w, acc[7]);
            acc[8]  = __fmaf_rn(q2, xv.x, acc[8]);  acc[9]  = __fmaf_rn(q2, xv.y, acc[9]);
            acc[10] = __fmaf_rn(q2, xv.z, acc[10]); acc[11] = __fmaf_rn(q2, xv.w, acc[11]);
            acc[12] = __fmaf_rn(q3, xv.x, acc[12]); acc[13] = __fmaf_rn(q3, xv.y, acc[13]);
            acc[14] = __fmaf_rn(q3, xv.z, acc[14]); acc[15] = __fmaf_rn(q3, xv.w, acc[15]);
        }
    }
#pragma unroll
    for (int o = 16; o > 0; o >>= 1) {
        s0 += __shfl_xor_sync(FULL, s0, o);
        s1 += __shfl_xor_sync(FULL, s1, o);
        s2 += __shfl_xor_sync(FULL, s2, o);
        s3 += __shfl_xor_sync(FULL, s3, o);
    }
    float r0 = __fdiv_rn(1.0f, __fadd_rn(s0, 1e-16f));
    float r1 = __fdiv_rn(1.0f, __fadd_rn(s1, 1e-16f));
    float r2 = __fdiv_rn(1.0f, __fadd_rn(s2, 1e-16f));
    float r3 = __fdiv_rn(1.0f, __fadd_rn(s3, 1e-16f));

    float* zp = &g_z[(size_t)v * 512 + lane * 4];
    *(float4*)&zp[0]   = make_float4(acc[0] * r0,  acc[1] * r0,  acc[2] * r0,  acc[3] * r0);
    *(float4*)&zp[128] = make_float4(acc[4] * r1,  acc[5] * r1,  acc[6] * r1,  acc[7] * r1);
    *(float4*)&zp[256] = make_float4(acc[8] * r2,  acc[9] * r2,  acc[10] * r2, acc[11] * r2);
    *(float4*)&zp[384] = make_float4(acc[12] * r3, acc[13] * r3, acc[14] * r3, acc[15] * r3);
}

// ---------------- layer 1: cp.async double-buffered 3xTF32 mma GEMM -> xb ----------------
// val[v][c] = BN(ELU(0.25 * sum_{K=512} z~[v][k]*Wcat[c][k] + b1[c]))
#define STR 36
#define BUF_FLOATS (128 * STR)                  // 4608
#define MMA_SMEM (4 * BUF_FLOATS * 4)           // A0,A1,B0,B1 raw fp32 = 73728 B

__global__ void k_gemm_mma(const float* __restrict__ W1, const float* __restrict__ bias,
                           const float* __restrict__ bng, const float* __restrict__ bnb,
                           const float* __restrict__ bnm, const float* __restrict__ bnv,
                           int n) {
    extern __shared__ float sm[];
    uint32_t sb = smem_to_u32(sm);
    int tid = threadIdx.x;
    int wid = tid >> 5, lane = tid & 31;
    int warp_m = wid >> 2;          // 0..1
    int warp_n = wid & 3;           // 0..3
    int grp = lane >> 2;            // 0..7
    int tig = lane & 3;             // 0..3
    int node0 = blockIdx.x * 128;

    float acc[4][4][4];
#pragma unroll
    for (int mf = 0; mf < 4; mf++)
#pragma unroll
        for (int nf = 0; nf < 4; nf++)
#pragma unroll
            for (int q = 0; q < 4; q++) acc[mf][nf][q] = 0.f;

    auto fill = [&](int buf, int ck) {
        int h = ck >> 2, kb = (ck & 3) * 32;
        for (int i = tid; i < 1024; i += 256) {
            int row = i >> 3;
            int kl = (i & 7) * 4;
            int nd = node0 + row;
            const float* srcA = (nd < n) ? &g_z[(size_t)nd * 512 + ck * 32 + kl] : g_z;
            cpasync16(sb + (uint32_t)((buf * BUF_FLOATS + row * STR + kl) * 4),
                      srcA, (nd < n) ? 16 : 0);
            cpasync16(sb + (uint32_t)(((2 + buf) * BUF_FLOATS + row * STR + kl) * 4),
                      &W1[(size_t)(h * 128 + row) * 128 + kb + kl], 16);
        }
    };

    fill(0, 0);
    CP_COMMIT();
    for (int ck = 0; ck < 16; ck++) {
        int buf = ck & 1;
        if (ck < 15) {
            fill(buf ^ 1, ck + 1);
            CP_COMMIT();
            CP_WAIT1();
        } else {
            CP_WAIT0();
        }
        __syncthreads();

        const float* A = sm + buf * BUF_FLOATS;
        const float* Bb = sm + (2 + buf) * BUF_FLOATS;
#pragma unroll
        for (int k8 = 0; k8 < 4; k8++) {
            int k0 = k8 * 8;
            uint32_t ah[4][4], al[4][4], bh[4][2], bl[4][2];
#pragma unroll
            for (int mf = 0; mf < 4; mf++) {
                int r0 = warp_m * 64 + mf * 16;
                float a0 = A[(r0 + grp) * STR + k0 + tig];
                float a1 = A[(r0 + grp + 8) * STR + k0 + tig];
                float a2 = A[(r0 + grp) * STR + k0 + tig + 4];
                float a3 = A[(r0 + grp + 8) * STR + k0 + tig + 4];
                float h0 = tf32r(a0), h1 = tf32r(a1), h2_ = tf32r(a2), h3 = tf32r(a3);
                ah[mf][0] = __float_as_uint(h0); al[mf][0] = __float_as_uint(a0 - h0);
                ah[mf][1] = __float_as_uint(h1); al[mf][1] = __float_as_uint(a1 - h1);
                ah[mf][2] = __float_as_uint(h2_); al[mf][2] = __float_as_uint(a2 - h2_);
                ah[mf][3] = __float_as_uint(h3); al[mf][3] = __float_as_uint(a3 - h3);
            }
#pragma unroll
            for (int nf = 0; nf < 4; nf++) {
                int c0 = warp_n * 32 + nf * 8;
                float b0 = Bb[(c0 + grp) * STR + k0 + tig];
                float b1 = Bb[(c0 + grp) * STR + k0 + tig + 4];
                float h0 = tf32r(b0), h1 = tf32r(b1);
                bh[nf][0] = __float_as_uint(h0); bl[nf][0] = __float_as_uint(b0 - h0);
                bh[nf][1] = __float_as_uint(h1); bl[nf][1] = __float_as_uint(b1 - h1);
            }
#pragma unroll
            for (int mf = 0; mf < 4; mf++)
#pragma unroll
                for (int nf = 0; nf < 4; nf++) {
                    mma_tf32(acc[mf][nf], ah[mf], bh[nf]);
                    mma_tf32(acc[mf][nf], ah[mf], bl[nf]);
                    mma_tf32(acc[mf][nf], al[mf], bh[nf]);
                }
        }
        __syncthreads();
    }

    // direct-store epilogue
#pragma unroll
    for (int mf = 0; mf < 4; mf++) {
        int r0 = node0 + warp_m * 64 + mf * 16 + grp;
#pragma unroll
        for (int half = 0; half < 2; half++) {
            int nd = r0 + half * 8;
            if (nd >= n) continue;
#pragma unroll
            for (int nf = 0; nf < 4; nf++) {
                int c0 = warp_n * 32 + nf * 8 + tig * 2;
                float vv[2];
#pragma unroll
                for (int q = 0; q < 2; q++) {
                    int c = c0 + q;
                    float val = __fmul_rn(acc[mf][nf][half * 2 + q], 0.25f);
                    val = __fadd_rn(val, bias[c]);
                    val = elu_acc(val);
                    float inv = __frsqrt_rn(__fadd_rn(bnv[c], 1e-5f));
                    val = __fadd_rn(__fmul_rn(__fmul_rn(__fsub_rn(val, bnm[c]), inv), bng[c]), bnb[c]);
                    vv[q] = val;
                }
                *(float2*)&g_xb[(size_t)nd * 128 + c0] = make_float2(vv[0], vv[1]);
            }
        }
    }
}

// ---------------- layer 2: fused h2 + scores ----------------
__global__ void k_l2(const float* __restrict__ W, const float* __restrict__ as_,
                     const float* __restrict__ ad_, int n) {
    int v = (blockIdx.x * blockDim.x + threadIdx.x) >> 5;
    int lane = threadIdx.x & 31;
    if (v >= n) return;
    float4 xv = *(const float4*)&g_xb[(size_t)v * 128 + lane * 4];
    float p[3];
#pragma unroll
    for (int o = 0; o < 3; o++) {
        float4 wv = *(const float4*)&W[o * 128 + lane * 4];
        float pp = __fmaf_rn(xv.x, wv.x, __fmaf_rn(xv.y, wv.y, __fmaf_rn(xv.z, wv.z, xv.w * wv.w)));
#pragma unroll
        for (int off = 16; off > 0; off >>= 1) pp += __shfl_xor_sync(FULL, pp, off);
        p[o] = pp;
    }
    if (lane == 0) {
        g_h2[v * 3 + 0] = p[0];
        g_h2[v * 3 + 1] = p[1];
        g_h2[v * 3 + 2] = p[2];
        g_s[v] = __fmaf_rn(p[0], as_[0], __fmaf_rn(p[1], as_[1], p[2] * as_[2]));
        g_d[v] = __fmaf_rn(p[0], ad_[0], __fmaf_rn(p[1], ad_[1], p[2] * ad_[2]));
    }
}

// ---------------- layer 2: single-pass softmax + aggregate + ODE epilogue ----------------
__global__ void k_smax2epi(const float* __restrict__ b2,
                           const float* __restrict__ kk, const float* __restrict__ dd,
                           const float* __restrict__ t00, const float* __restrict__ u00,
                           const float* __restrict__ t, float* __restrict__ out, int n) {
    int v = (blockIdx.x * blockDim.x + threadIdx.x) >> 5;
    int lane = threadIdx.x & 31;
    if (v >= n) return;
    int beg = g_rowptr[v], end = g_rowptr[v + 1];
    float sd = g_d[v];

    float sum = 0.f, a0 = 0.f, a1 = 0.f, a2 = 0.f;
    for (int idx = beg + lane; idx < end; idx += 32) {
        int s = g_csrs[idx];
        float p = exp_acc(lrelu(g_s[s] + sd));
        sum += p;
        a0 = __fmaf_rn(p, g_h2[s * 3 + 0], a0);
        a1 = __fmaf_rn(p, g_h2[s * 3 + 1], a1);
        a2 = __fmaf_rn(p, g_h2[s * 3 + 2], a2);
    }
#pragma unroll
    for (int o = 16; o > 0; o >>= 1) {
        sum += __shfl_xor_sync(FULL, sum, o);
        a0 += __shfl_xor_sync(FULL, a0, o);
        a1 += __shfl_xor_sync(FULL, a1, o);
        a2 += __shfl_xor_sync(FULL, a2, o);
    }
    if (lane == 0) {
        float denom = __fadd_rn(sum, 1e-16f);
        float ar  = elu_acc(__fadd_rn(__fdiv_rn(a0, denom), b2[0]));
        float gam = elu_acc(__fadd_rn(__fdiv_rn(a1, denom), b2[1]));
        float bet = elu_acc(__fadd_rn(__fdiv_rn(a2, denom), b2[2]));

        float tt = t[v];
        float K = kk[0], D = dd[0], T0 = t00[0], U0 = u00[0];

        float z = __fmul_rn(K, __fsub_rn(__fsub_rn(tt, T0), D));
        float S = __fdiv_rn(1.0f, __fadd_rn(1.0f, exp_acc(-z)));
        float oneMS = __fsub_rn(1.0f, S);

        float eb  = exp_acc(__fmul_rn(-bet, tt));
        float eg  = exp_acc(__fmul_rn(-gam, tt));
        float tmt0 = __fsub_rn(tt, T0);
        float ebs = exp_acc(__fmul_rn(-bet, tmt0));
        float egs = exp_acc(__fmul_rn(-gam, tmt0));
        float ab = __fdiv_rn(ar, bet);
        float ag = __fdiv_rn(ar, gam);

        float tu = __fadd_rn(
                     __fadd_rn(__fmul_rn(__fmul_rn(ab, __fsub_rn(1.0f, eb)), oneMS),
                               __fmul_rn(ab, S)),
                     __fmul_rn(__fsub_rn(__fmul_rn(U0, ebs), ab), S));

        float gmb = __fsub_rn(gam, bet);
        float term1 = __fadd_rn(__fmul_rn(ag, __fsub_rn(1.0f, eg)),
                                __fmul_rn(__fdiv_rn(ar, gmb), __fsub_rn(eg, eb)));
        float term3 = __fmul_rn(__fmul_rn(__fdiv_rn(__fmul_rn(bet, U0), gmb),
                                          __fsub_rn(egs, ebs)), S);
        float ts = __fadd_rn(__fadd_rn(__fmul_rn(term1, oneMS), __fmul_rn(ag, S)), term3);

        out[v] = tu;
        out[n + v] = ts;
    }
}

// ---------------- launch ----------------
extern "C" void kernel_launch(void* const* d_in, const int* in_sizes, int n_in,
                              void* d_out, int out_size) {
    int off = (n_in >= 28) ? 0 : -1;
    const float* x    = (const float*)d_in[0];
    const int*   ei   = (const int*)d_in[1];
    const float* W0   = (const float*)d_in[3 + off];
    const float* as0  = (const float*)d_in[4 + off];
    const float* ad0  = (const float*)d_in[5 + off];
    const float* b0   = (const float*)d_in[6 + off];
    const float* W1   = (const float*)d_in[7 + off];
    const float* as1  = (const float*)d_in[8 + off];
    const float* ad1  = (const float*)d_in[9 + off];
    const float* b1   = (const float*)d_in[10 + off];
    const float* W2   = (const float*)d_in[11 + off];
    const float* as2  = (const float*)d_in[12 + off];
    const float* ad2  = (const float*)d_in[13 + off];
    const float* b2   = (const float*)d_in[14 + off];
    const float* bng0 = (const float*)d_in[15 + off];
    const float* bnb0 = (const float*)d_in[16 + off];
    const float* bnm0 = (const float*)d_in[17 + off];
    const float* bnv0 = (const float*)d_in[18 + off];
    const float* bng1 = (const float*)d_in[19 + off];
    const float* bnb1 = (const float*)d_in[20 + off];
    const float* bnm1 = (const float*)d_in[21 + off];
    const float* bnv1 = (const float*)d_in[22 + off];
    const float* kk   = (const float*)d_in[23 + off];
    const float* dd   = (const float*)d_in[24 + off];
    const float* t00  = (const float*)d_in[25 + off];
    const float* u00  = (const float*)d_in[26 + off];
    const float* t    = (const float*)d_in[27 + off];
    float* out = (float*)d_out;

    int n = in_sizes[0] / 2;
    int e = in_sizes[1] / 2;
    int m = e + n;

    const int B = 256;
    auto nb = [](long long x_, int b) { return (int)((x_ + b - 1) / b); };
    int nwb = nb((long long)n * 32, B);   // warp-per-node grids

    cudaFuncSetAttribute(k_gemm_mma, cudaFuncAttributeMaxDynamicSharedMemorySize, MMA_SMEM);

    // CSR build + attention-vector precompute
    k_edges_count<<<nb(m, B), B>>>(ei, e, m);
    k_scan<<<1, 1024>>>(n, m);
    k_fill<<<nb(m, B), B>>>(m);
    k_pre<<<130, 256>>>(W0, as0, ad0, W1, as1, ad1);

    // ---- layer 0 (h never materialized) ----
    k_score0<<<nb(n, B), B>>>(x, n);
    k_l0agg<<<nwb, B>>>(x, W0, b0, bng0, bnb0, bnm0, bnv0, n);

    // ---- layer 1 (aggregate z first, project after on tensor cores) ----
    k_score1<<<nwb, B>>>(n);
    k_agg1<<<nwb, B>>>(n);
    k_gemm_mma<<<nb(n, 128), 256, MMA_SMEM>>>(W1, b1, bng1, bnb1, bnm1, bnv1, n);

    // ---- layer 2 + epilogue ----
    k_l2<<<nwb, B>>>(W2, as2, ad2, n);
    k_smax2epi<<<nwb, B>>>(b2, kk, dd, t00, u00, t, out, n);
}

// round 16
// speedup vs baseline: 1.3640x; 1.0034x over previous
#include <cuda_runtime.h>
#include <math.h>
#include <cstdint>

#define NN 20000
#define EE 320000
#define MMX (EE + NN)
#define FULL 0xffffffffu

// ---------------- scratch ----------------
__device__ float g_z[NN * 512];          // layer-1 aggregated z (pre-divided by sum)
__device__ float g_xa[NN * 128];
__device__ float g_xb[NN * 128];
__device__ float g_s[NN * 4];            // layer-0 scores (src part)
__device__ float g_d[NN * 4];            // layer-0 scores (dst part)
__device__ float g_s1[NN * 4];           // layer-1 scores
__device__ float g_d1[NN * 4];
__device__ float g_h2[NN * 3];
__device__ int g_deg[NN];                // statically zero-initialized; re-zeroed by k_scan
__device__ int g_rowptr[NN + 1];
__device__ int g_cursor[NN];
__device__ int g_csrs[MMX];              // CSR by dst: src node per slot
__device__ float g_A0[16];               // layer0: As(h,i) [0..7], Ad(h,i) [8..15]
__device__ float g_ws[512];              // layer1: w~s_h[k] = W1_h^T as_h
__device__ float g_wd[512];

// ---------------- accurate exp/expm1/elu ----------------
__device__ __forceinline__ float exp_acc(float x) {
    x = fminf(fmaxf(x, -87.0f), 87.0f);
    float kf = rintf(__fmul_rn(x, 1.4426950408889634f));
    float r = __fmaf_rn(kf, -0.69314718246459960938f, x);
    r = __fmaf_rn(kf, 1.9046542743622637e-9f, r);
    float p = 1.9841269841269841e-4f;
    p = __fmaf_rn(p, r, 1.3888888888888889e-3f);
    p = __fmaf_rn(p, r, 8.3333333333333332e-3f);
    p = __fmaf_rn(p, r, 4.1666666666666664e-2f);
    p = __fmaf_rn(p, r, 1.6666666666666666e-1f);
    p = __fmaf_rn(p, r, 0.5f);
    p = __fmaf_rn(p, r, 1.0f);
    p = __fmaf_rn(p, r, 1.0f);
    int ik = (int)kf;
    float s = __int_as_float((ik + 127) << 23);
    return __fmul_rn(p, s);
}
__device__ __forceinline__ float expm1_acc(float x) {
    if (x < -0.34657359f) return __fadd_rn(exp_acc(x), -1.0f);
    float p = 1.9841269841269841e-4f;
    p = __fmaf_rn(p, x, 1.3888888888888889e-3f);
    p = __fmaf_rn(p, x, 8.3333333333333332e-3f);
    p = __fmaf_rn(p, x, 4.1666666666666664e-2f);
    p = __fmaf_rn(p, x, 1.6666666666666666e-1f);
    p = __fmaf_rn(p, x, 0.5f);
    p = __fmaf_rn(p, x, 1.0f);
    return __fmul_rn(p, x);
}
__device__ __forceinline__ float elu_acc(float x) {
    return x > 0.f ? x : expm1_acc(x);
}
__device__ __forceinline__ float lrelu(float x) {
    return x >= 0.f ? x : 0.2f * x;
}
__device__ __forceinline__ float tf32r(float x) {
    float r;
    asm("cvt.rna.tf32.f32 %0, %1;" : "=f"(r) : "f"(x));
    return r;
}

// ---------------- warp mma: m16n8k8 tf32 ----------------
__device__ __forceinline__ void mma_tf32(float* c, const uint32_t* a, const uint32_t* b) {
    asm volatile(
        "mma.sync.aligned.m16n8k8.row.col.f32.tf32.tf32.f32 "
        "{%0,%1,%2,%3}, {%4,%5,%6,%7}, {%8,%9}, {%0,%1,%2,%3};"
        : "+f"(c[0]), "+f"(c[1]), "+f"(c[2]), "+f"(c[3])
        : "r"(a[0]), "r"(a[1]), "r"(a[2]), "r"(a[3]), "r"(b[0]), "r"(b[1]));
}
__device__ __forceinline__ uint32_t smem_to_u32(const void* p) {
    uint32_t a;
    asm("{ .reg .u64 t; cvta.to.shared.u64 t, %1; cvt.u32.u64 %0, t; }" : "=r"(a) : "l"(p));
    return a;
}
__device__ __forceinline__ void cpasync16(uint32_t dst, const void* src, int srcsize) {
    asm volatile("cp.async.cg.shared.global [%0], [%1], 16, %2;"
                 :: "r"(dst), "l"(src), "r"(srcsize));
}
#define CP_COMMIT() asm volatile("cp.async.commit_group;" ::: "memory")
#define CP_WAIT1() asm volatile("cp.async.wait_group 1;" ::: "memory")
#define CP_WAIT0() asm volatile("cp.async.wait_group 0;" ::: "memory")

// ---------------- CSR build (edge_index read directly; no edge-list copy) ----------------
__global__ void k_count(const int* __restrict__ ei, int e, int m) {
    int i = blockIdx.x * blockDim.x + threadIdx.x;
    if (i >= m) return;
    int d = (i < e) ? ei[e + i] : (i - e);
    atomicAdd(&g_deg[d], 1);
}
__global__ void k_scan(int n, int m) {
    __shared__ int wsum[32];
    int t = threadIdx.x;
    int lane = t & 31, wid = t >> 5;
    int chunk = (n + 1023) / 1024;
    int b0 = t * chunk;
    int b1 = min(b0 + chunk, n);
    int s = 0;
    for (int i = b0; i < b1; i++) s += g_deg[i];
    int v = s;
#pragma unroll
    for (int o = 1; o < 32; o <<= 1) {
        int u = __shfl_up_sync(FULL, v, o);
        if (lane >= o) v += u;
    }
    if (lane == 31) wsum[wid] = v;
    __syncthreads();
    if (wid == 0) {
        int w = wsum[lane];
#pragma unroll
        for (int o = 1; o < 32; o <<= 1) {
            int u = __shfl_up_sync(FULL, w, o);
            if (lane >= o) w += u;
        }
        wsum[lane] = w;
    }
    __syncthreads();
    int run = (v - s) + (wid > 0 ? wsum[wid - 1] : 0);
    for (int i = b0; i < b1; i++) {
        g_rowptr[i] = run;
        g_cursor[i] = run;
        run += g_deg[i];
        g_deg[i] = 0;     // reset for next replay
    }
    if (t == 0) g_rowptr[n] = m;
}
__global__ void k_fill(const int* __restrict__ ei, int e, int m) {
    int i = blockIdx.x * blockDim.x + threadIdx.x;
    if (i >= m) return;
    int s, d;
    if (i < e) { s = ei[i]; d = ei[e + i]; }
    else       { s = i - e; d = i - e; }
    int pos = atomicAdd(&g_cursor[d], 1);
    g_csrs[pos] = s;
}

// ---------------- parallel precompute of projected attention vectors ----------------
__global__ void k_pre(const float* __restrict__ W0, const float* __restrict__ as0,
                      const float* __restrict__ ad0,
                      const float* __restrict__ W1, const float* __restrict__ as1,
                      const float* __restrict__ ad1) {
    int w = (blockIdx.x * blockDim.x + threadIdx.x) >> 5;
    int lane = threadIdx.x & 31;
    if (w < 1024) {
        int o = w & 511;
        int h = o >> 7, k = o & 127;
        const float* a = (w < 512) ? as1 : ad1;
        float acc = 0.f;
#pragma unroll
        for (int i = 0; i < 4; i++) {
            int c = lane + i * 32;
            acc = __fmaf_rn(a[h * 128 + c], W1[(size_t)(h * 128 + c) * 128 + k], acc);
        }
#pragma unroll
        for (int o2 = 16; o2 > 0; o2 >>= 1) acc += __shfl_xor_sync(FULL, acc, o2);
        if (lane == 0) {
            if (w < 512) g_ws[o] = acc;
            else g_wd[o] = acc;
        }
    } else if (w < 1040) {
        int t = w - 1024;           // 0..15
        int h = t & 3, i = (t >> 2) & 1;
        const float* a = (t < 8) ? as0 : ad0;
        float acc = 0.f;
#pragma unroll
        for (int j = 0; j < 4; j++) {
            int c = lane + j * 32;
            acc = __fmaf_rn(a[h * 128 + c], W0[(h * 128 + c) * 2 + i], acc);
        }
#pragma unroll
        for (int o2 = 16; o2 > 0; o2 >>= 1) acc += __shfl_xor_sync(FULL, acc, o2);
        if (lane == 0) g_A0[(t < 8 ? 0 : 8) + h * 2 + i] = acc;
    }
}

// ---------------- layer 0 scores ----------------
__global__ void k_score0(const float* __restrict__ x, int n) {
    int v = blockIdx.x * blockDim.x + threadIdx.x;
    if (v >= n) return;
    float x0 = x[2 * v], x1 = x[2 * v + 1];
    float4 s, d;
    s.x = __fmaf_rn(x0, g_A0[0], x1 * g_A0[1]);
    s.y = __fmaf_rn(x0, g_A0[2], x1 * g_A0[3]);
    s.z = __fmaf_rn(x0, g_A0[4], x1 * g_A0[5]);
    s.w = __fmaf_rn(x0, g_A0[6], x1 * g_A0[7]);
    d.x = __fmaf_rn(x0, g_A0[8],  x1 * g_A0[9]);
    d.y = __fmaf_rn(x0, g_A0[10], x1 * g_A0[11]);
    d.z = __fmaf_rn(x0, g_A0[12], x1 * g_A0[13]);
    d.w = __fmaf_rn(x0, g_A0[14], x1 * g_A0[15]);
    *(float4*)&g_s[v * 4] = s;
    *(float4*)&g_d[v * 4] = d;
}

// ---------------- layer 0: softmax + rank-2 aggregate + finalize + FUSED layer-1 scores ----
__global__ void k_l0agg(const float* __restrict__ x, const float* __restrict__ W0,
                        const float* __restrict__ bias,
                        const float* __restrict__ bng, const float* __restrict__ bnb,
                        const float* __restrict__ bnm, const float* __restrict__ bnv, int n) {
    int v = (blockIdx.x * blockDim.x + threadIdx.x) >> 5;
    int lane = threadIdx.x & 31;
    if (v >= n) return;
    int beg = g_rowptr[v], end = g_rowptr[v + 1];
    float4 dv = *(const float4*)&g_d[v * 4];

    float s0 = 0.f, s1 = 0.f, s2 = 0.f, s3 = 0.f;
    float zx0 = 0.f, zx1 = 0.f, zx2 = 0.f, zx3 = 0.f;
    float zy0 = 0.f, zy1 = 0.f, zy2 = 0.f, zy3 = 0.f;
    for (int idx = beg + lane; idx < end; idx += 32) {
        int s = g_csrs[idx];
        float4 sv = *(const float4*)&g_s[s * 4];
        float p0 = exp_acc(lrelu(sv.x + dv.x));
        float p1 = exp_acc(lrelu(sv.y + dv.y));
        float p2 = exp_acc(lrelu(sv.z + dv.z));
        float p3 = exp_acc(lrelu(sv.w + dv.w));
        s0 += p0; s1 += p1; s2 += p2; s3 += p3;
        float2 xv = *(const float2*)&x[2 * s];
        zx0 = __fmaf_rn(p0, xv.x, zx0); zy0 = __fmaf_rn(p0, xv.y, zy0);
        zx1 = __fmaf_rn(p1, xv.x, zx1); zy1 = __fmaf_rn(p1, xv.y, zy1);
        zx2 = __fmaf_rn(p2, xv.x, zx2); zy2 = __fmaf_rn(p2, xv.y, zy2);
        zx3 = __fmaf_rn(p3, xv.x, zx3); zy3 = __fmaf_rn(p3, xv.y, zy3);
    }
#pragma unroll
    for (int o = 16; o > 0; o >>= 1) {
        s0 += __shfl_xor_sync(FULL, s0, o);  s1 += __shfl_xor_sync(FULL, s1, o);
        s2 += __shfl_xor_sync(FULL, s2, o);  s3 += __shfl_xor_sync(FULL, s3, o);
        zx0 += __shfl_xor_sync(FULL, zx0, o); zx1 += __shfl_xor_sync(FULL, zx1, o);
        zx2 += __shfl_xor_sync(FULL, zx2, o); zx3 += __shfl_xor_sync(FULL, zx3, o);
        zy0 += __shfl_xor_sync(FULL, zy0, o); zy1 += __shfl_xor_sync(FULL, zy1, o);
        zy2 += __shfl_xor_sync(FULL, zy2, o); zy3 += __shfl_xor_sync(FULL, zy3, o);
    }
    float d0 = __fadd_rn(s0, 1e-16f);
    float d1 = __fadd_rn(s1, 1e-16f);
    float d2 = __fadd_rn(s2, 1e-16f);
    float d3 = __fadd_rn(s3, 1e-16f);
    float ZX[4] = {zx0, zx1, zx2, zx3};
    float ZY[4] = {zy0, zy1, zy2, zy3};
    float DD[4] = {d0, d1, d2, d3};

    int c = lane * 4;
    float vals[4];
#pragma unroll
    for (int j = 0; j < 4; j++) {
        int cc = c + j;
        float a = 0.f;
#pragma unroll
        for (int h = 0; h < 4; h++) {
            float w0 = W0[(h * 128 + cc) * 2];
            float w1 = W0[(h * 128 + cc) * 2 + 1];
            float tmp = __fmaf_rn(w0, ZX[h], __fmul_rn(w1, ZY[h]));
            a = __fadd_rn(a, __fdiv_rn(tmp, DD[h]));
        }
        float val = __fmul_rn(a, 0.25f);
        val = __fadd_rn(val, bias[cc]);
        val = elu_acc(val);
        float inv = __frsqrt_rn(__fadd_rn(bnv[cc], 1e-5f));
        val = __fadd_rn(__fmul_rn(__fmul_rn(__fsub_rn(val, bnm[cc]), inv), bng[cc]), bnb[cc]);
        vals[j] = val;
    }
    *(float4*)&g_xa[(size_t)v * 128 + c] = make_float4(vals[0], vals[1], vals[2], vals[3]);

    // ---- fused layer-1 scores: s1[v,h] = xa[v] . w~s_h  (xa row is in-register) ----
    float sp[4], dp[4];
#pragma unroll
    for (int hd = 0; hd < 4; hd++) {
        float4 wv = *(const float4*)&g_ws[hd * 128 + c];
        float4 uv = *(const float4*)&g_wd[hd * 128 + c];
        float s = vals[0] * wv.x + vals[1] * wv.y + vals[2] * wv.z + vals[3] * wv.w;
        float d = vals[0] * uv.x + vals[1] * uv.y + vals[2] * uv.z + vals[3] * uv.w;
#pragma unroll
        for (int o = 16; o > 0; o >>= 1) {
            s += __shfl_xor_sync(FULL, s, o);
            d += __shfl_xor_sync(FULL, d, o);
        }
        sp[hd] = s;
        dp[hd] = d;
    }
    if (lane == 0) {
        *(float4*)&g_s1[v * 4] = make_float4(sp[0], sp[1], sp[2], sp[3]);
        *(float4*)&g_d1[v * 4] = make_float4(dp[0], dp[1], dp[2], dp[3]);
    }
}

// ---------------- layer 1: single-pass softmax + z-aggregate ----------------
__global__ void k_agg1(int n) {
    int v = (blockIdx.x * blockDim.x + threadIdx.x) >> 5;
    int lane = threadIdx.x & 31;
    if (v >= n) return;
    int beg = g_rowptr[v], end = g_rowptr[v + 1];
    float4 dv = *(const float4*)&g_d1[v * 4];

    float acc[16];
#pragma unroll
    for (int i = 0; i < 16; i++) acc[i] = 0.f;
    float s0 = 0.f, s1 = 0.f, s2 = 0.f, s3 = 0.f;

    for (int base = beg; base < end; base += 32) {
        int idx = base + lane;
        int sv = 0;
        float p0 = 0.f, p1 = 0.f, p2 = 0.f, p3 = 0.f;
        if (idx < end) {
            sv = g_csrs[idx];
            float4 ss = *(const float4*)&g_s1[sv * 4];
            p0 = exp_acc(lrelu(ss.x + dv.x));
            p1 = exp_acc(lrelu(ss.y + dv.y));
            p2 = exp_acc(lrelu(ss.z + dv.z));
            p3 = exp_acc(lrelu(ss.w + dv.w));
            s0 += p0; s1 += p1; s2 += p2; s3 += p3;
        }
        int cnt = min(32, end - base);
        for (int t = 0; t < cnt; t++) {
            int s = __shfl_sync(FULL, sv, t);
            float q0 = __shfl_sync(FULL, p0, t);
            float q1 = __shfl_sync(FULL, p1, t);
            float q2 = __shfl_sync(FULL, p2, t);
            float q3 = __shfl_sync(FULL, p3, t);
            float4 xv = *(const float4*)&g_xa[(size_t)s * 128 + lane * 4];
            acc[0]  = __fmaf_rn(q0, xv.x, acc[0]);  acc[1]  = __fmaf_rn(q0, xv.y, acc[1]);
            acc[2]  = __fmaf_rn(q0, xv.z, acc[2]);  acc[3]  = __fmaf_rn(q0, xv.w, acc[3]);
            acc[4]  = __fmaf_rn(q1, xv.x, acc[4]);  acc[5]  = __fmaf_rn(q1, xv.y, acc[5]);
            acc[6]  = __fmaf_rn(q1, xv.z, acc[6]);  acc[7]  = __fmaf_rn(q1, xv.w, acc[7]);
            acc[8]  = __fmaf_rn(q2, xv.x, acc[8]);  acc[9]  = __fmaf_rn(q2, xv.y, acc[9]);
            acc[10] = __fmaf_rn(q2, xv.z, acc[10]); acc[11] = __fmaf_rn(q2, xv.w, acc[11]);
            acc[12] = __fmaf_rn(q3, xv.x, acc[12]); acc[13] = __fmaf_rn(q3, xv.y, acc[13]);
            acc[14] = __fmaf_rn(q3, xv.z, acc[14]); acc[15] = __fmaf_rn(q3, xv.w, acc[15]);
        }
    }
#pragma unroll
    for (int o = 16; o > 0; o >>= 1) {
        s0 += __shfl_xor_sync(FULL, s0, o);
        s1 += __shfl_xor_sync(FULL, s1, o);
        s2 += __shfl_xor_sync(FULL, s2, o);
        s3 += __shfl_xor_sync(FULL, s3, o);
    }
    float r0 = __fdiv_rn(1.0f, __fadd_rn(s0, 1e-16f));
    float r1 = __fdiv_rn(1.0f, __fadd_rn(s1, 1e-16f));
    float r2 = __fdiv_rn(1.0f, __fadd_rn(s2, 1e-16f));
    float r3 = __fdiv_rn(1.0f, __fadd_rn(s3, 1e-16f));

    float* zp = &g_z[(size_t)v * 512 + lane * 4];
    *(float4*)&zp[0]   = make_float4(acc[0] * r0,  acc[1] * r0,  acc[2] * r0,  acc[3] * r0);
    *(float4*)&zp[128] = make_float4(acc[4] * r1,  acc[5] * r1,  acc[6] * r1,  acc[7] * r1);
    *(float4*)&zp[256] = make_float4(acc[8] * r2,  acc[9] * r2,  acc[10] * r2, acc[11] * r2);
    *(float4*)&zp[384] = make_float4(acc[12] * r3, acc[13] * r3, acc[14] * r3, acc[15] * r3);
}

// ---------------- layer 1: cp.async double-buffered 3xTF32 mma GEMM -> xb ----------------
#define STR 36
#define BUF_FLOATS (128 * STR)                  // 4608
#define MMA_SMEM (4 * BUF_FLOATS * 4)           // A0,A1,B0,B1 raw fp32 = 73728 B

__global__ void k_gemm_mma(const float* __restrict__ W1, const float* __restrict__ bias,
                           const float* __restrict__ bng, const float* __restrict__ bnb,
                           const float* __restrict__ bnm, const float* __restrict__ bnv,
                           int n) {
    extern __shared__ float sm[];
    uint32_t sb = smem_to_u32(sm);
    int tid = threadIdx.x;
    int wid = tid >> 5, lane = tid & 31;
    int warp_m = wid >> 2;          // 0..1
    int warp_n = wid & 3;           // 0..3
    int grp = lane >> 2;            // 0..7
    int tig = lane & 3;             // 0..3
    int node0 = blockIdx.x * 128;

    float acc[4][4][4];
#pragma unroll
    for (int mf = 0; mf < 4; mf++)
#pragma unroll
        for (int nf = 0; nf < 4; nf++)
#pragma unroll
            for (int q = 0; q < 4; q++) acc[mf][nf][q] = 0.f;

    auto fill = [&](int buf, int ck) {
        int h = ck >> 2, kb = (ck & 3) * 32;
        for (int i = tid; i < 1024; i += 256) {
            int row = i >> 3;
            int kl = (i & 7) * 4;
            int nd = node0 + row;
            const float* srcA = (nd < n) ? &g_z[(size_t)nd * 512 + ck * 32 + kl] : g_z;
            cpasync16(sb + (uint32_t)((buf * BUF_FLOATS + row * STR + kl) * 4),
                      srcA, (nd < n) ? 16 : 0);
            cpasync16(sb + (uint32_t)(((2 + buf) * BUF_FLOATS + row * STR + kl) * 4),
                      &W1[(size_t)(h * 128 + row) * 128 + kb + kl], 16);
        }
    };

    fill(0, 0);
    CP_COMMIT();
    for (int ck = 0; ck < 16; ck++) {
        int buf = ck & 1;
        if (ck < 15) {
            fill(buf ^ 1, ck + 1);
            CP_COMMIT();
            CP_WAIT1();
        } else {
            CP_WAIT0();
        }
        __syncthreads();

        const float* A = sm + buf * BUF_FLOATS;
        const float* Bb = sm + (2 + buf) * BUF_FLOATS;
#pragma unroll
        for (int k8 = 0; k8 < 4; k8++) {
            int k0 = k8 * 8;
            uint32_t ah[4][4], al[4][4], bh[4][2], bl[4][2];
#pragma unroll
            for (int mf = 0; mf < 4; mf++) {
                int r0 = warp_m * 64 + mf * 16;
                float a0 = A[(r0 + grp) * STR + k0 + tig];
                float a1 = A[(r0 + grp + 8) * STR + k0 + tig];
                float a2 = A[(r0 + grp) * STR + k0 + tig + 4];
                float a3 = A[(r0 + grp + 8) * STR + k0 + tig + 4];
                float h0 = tf32r(a0), h1 = tf32r(a1), h2_ = tf32r(a2), h3 = tf32r(a3);
                ah[mf][0] = __float_as_uint(h0); al[mf][0] = __float_as_uint(a0 - h0);
                ah[mf][1] = __float_as_uint(h1); al[mf][1] = __float_as_uint(a1 - h1);
                ah[mf][2] = __float_as_uint(h2_); al[mf][2] = __float_as_uint(a2 - h2_);
                ah[mf][3] = __float_as_uint(h3); al[mf][3] = __float_as_uint(a3 - h3);
            }
#pragma unroll
            for (int nf = 0; nf < 4; nf++) {
                int c0 = warp_n * 32 + nf * 8;
                float b0 = Bb[(c0 + grp) * STR + k0 + tig];
                float b1 = Bb[(c0 + grp) * STR + k0 + tig + 4];
                float h0 = tf32r(b0), h1 = tf32r(b1);
                bh[nf][0] = __float_as_uint(h0); bl[nf][0] = __float_as_uint(b0 - h0);
                bh[nf][1] = __float_as_uint(h1); bl[nf][1] = __float_as_uint(b1 - h1);
            }
#pragma unroll
            for (int mf = 0; mf < 4; mf++)
#pragma unroll
                for (int nf = 0; nf < 4; nf++) {
                    mma_tf32(acc[mf][nf], ah[mf], bh[nf]);
                    mma_tf32(acc[mf][nf], ah[mf], bl[nf]);
                    mma_tf32(acc[mf][nf], al[mf], bh[nf]);
                }
        }
        __syncthreads();
    }

    // direct-store epilogue
#pragma unroll
    for (int mf = 0; mf < 4; mf++) {
        int r0 = node0 + warp_m * 64 + mf * 16 + grp;
#pragma unroll
        for (int half = 0; half < 2; half++) {
            int nd = r0 + half * 8;
            if (nd >= n) continue;
#pragma unroll
            for (int nf = 0; nf < 4; nf++) {
                int c0 = warp_n * 32 + nf * 8 + tig * 2;
                float vv[2];
#pragma unroll
                for (int q = 0; q < 2; q++) {
                    int c = c0 + q;
                    float val = __fmul_rn(acc[mf][nf][half * 2 + q], 0.25f);
                    val = __fadd_rn(val, bias[c]);
                    val = elu_acc(val);
                    float inv = __frsqrt_rn(__fadd_rn(bnv[c], 1e-5f));
                    val = __fadd_rn(__fmul_rn(__fmul_rn(__fsub_rn(val, bnm[c]), inv), bng[c]), bnb[c]);
                    vv[q] = val;
                }
                *(float2*)&g_xb[(size_t)nd * 128 + c0] = make_float2(vv[0], vv[1]);
            }
        }
    }
}

// ---------------- layer 2: fused h2 + scores ----------------
__global__ void k_l2(const float* __restrict__ W, const float* __restrict__ as_,
                     const float* __restrict__ ad_, int n) {
    int v = (blockIdx.x * blockDim.x + threadIdx.x) >> 5;
    int lane = threadIdx.x & 31;
    if (v >= n) return;
    float4 xv = *(const float4*)&g_xb[(size_t)v * 128 + lane * 4];
    float p[3];
#pragma unroll
    for (int o = 0; o < 3; o++) {
        float4 wv = *(const float4*)&W[o * 128 + lane * 4];
        float pp = __fmaf_rn(xv.x, wv.x, __fmaf_rn(xv.y, wv.y, __fmaf_rn(xv.z, wv.z, xv.w * wv.w)));
#pragma unroll
        for (int off = 16; off > 0; off >>= 1) pp += __shfl_xor_sync(FULL, pp, off);
        p[o] = pp;
    }
    if (lane == 0) {
        g_h2[v * 3 + 0] = p[0];
        g_h2[v * 3 + 1] = p[1];
        g_h2[v * 3 + 2] = p[2];
        g_s[v] = __fmaf_rn(p[0], as_[0], __fmaf_rn(p[1], as_[1], p[2] * as_[2]));
        g_d[v] = __fmaf_rn(p[0], ad_[0], __fmaf_rn(p[1], ad_[1], p[2] * ad_[2]));
    }
}

// ---------------- layer 2: single-pass softmax + aggregate + ODE epilogue ----------------
__global__ void k_smax2epi(const float* __restrict__ b2,
                           const float* __restrict__ kk, const float* __restrict__ dd,
                           const float* __restrict__ t00, const float* __restrict__ u00,
                           const float* __restrict__ t, float* __restrict__ out, int n) {
    int v = (blockIdx.x * blockDim.x + threadIdx.x) >> 5;
    int lane = threadIdx.x & 31;
    if (v >= n) return;
    int beg = g_rowptr[v], end = g_rowptr[v + 1];
    float sd = g_d[v];

    float sum = 0.f, a0 = 0.f, a1 = 0.f, a2 = 0.f;
    for (int idx = beg + lane; idx < end; idx += 32) {
        int s = g_csrs[idx];
        float p = exp_acc(lrelu(g_s[s] + sd));
        sum += p;
        a0 = __fmaf_rn(p, g_h2[s * 3 + 0], a0);
        a1 = __fmaf_rn(p, g_h2[s * 3 + 1], a1);
        a2 = __fmaf_rn(p, g_h2[s * 3 + 2], a2);
    }
#pragma unroll
    for (int o = 16; o > 0; o >>= 1) {
        sum += __shfl_xor_sync(FULL, sum, o);
        a0 += __shfl_xor_sync(FULL, a0, o);
        a1 += __shfl_xor_sync(FULL, a1, o);
        a2 += __shfl_xor_sync(FULL, a2, o);
    }
    if (lane == 0) {
        float denom = __fadd_rn(sum, 1e-16f);
        float ar  = elu_acc(__fadd_rn(__fdiv_rn(a0, denom), b2[0]));
        float gam = elu_acc(__fadd_rn(__fdiv_rn(a1, denom), b2[1]));
        float bet = elu_acc(__fadd_rn(__fdiv_rn(a2, denom), b2[2]));

        float tt = t[v];
        float K = kk[0], D = dd[0], T0 = t00[0], U0 = u00[0];

        float z = __fmul_rn(K, __fsub_rn(__fsub_rn(tt, T0), D));
        float S = __fdiv_rn(1.0f, __fadd_rn(1.0f, exp_acc(-z)));
        float oneMS = __fsub_rn(1.0f, S);

        float eb  = exp_acc(__fmul_rn(-bet, tt));
        float eg  = exp_acc(__fmul_rn(-gam, tt));
        float tmt0 = __fsub_rn(tt, T0);
        float ebs = exp_acc(__fmul_rn(-bet, tmt0));
        float egs = exp_acc(__fmul_rn(-gam, tmt0));
        float ab = __fdiv_rn(ar, bet);
        float ag = __fdiv_rn(ar, gam);

        float tu = __fadd_rn(
                     __fadd_rn(__fmul_rn(__fmul_rn(ab, __fsub_rn(1.0f, eb)), oneMS),
                               __fmul_rn(ab, S)),
                     __fmul_rn(__fsub_rn(__fmul_rn(U0, ebs), ab), S));

        float gmb = __fsub_rn(gam, bet);
        float term1 = __fadd_rn(__fmul_rn(ag, __fsub_rn(1.0f, eg)),
                                __fmul_rn(__fdiv_rn(ar, gmb), __fsub_rn(eg, eb)));
        float term3 = __fmul_rn(__fmul_rn(__fdiv_rn(__fmul_rn(bet, U0), gmb),
                                          __fsub_rn(egs, ebs)), S);
        float ts = __fadd_rn(__fadd_rn(__fmul_rn(term1, oneMS), __fmul_rn(ag, S)), term3);

        out[v] = tu;
        out[n + v] = ts;
    }
}

// ---------------- launch ----------------
extern "C" void kernel_launch(void* const* d_in, const int* in_sizes, int n_in,
                              void* d_out, int out_size) {
    int off = (n_in >= 28) ? 0 : -1;
    const float* x    = (const float*)d_in[0];
    const int*   ei   = (const int*)d_in[1];
    const float* W0   = (const float*)d_in[3 + off];
    const float* as0  = (const float*)d_in[4 + off];
    const float* ad0  = (const float*)d_in[5 + off];
    const float* b0   = (const float*)d_in[6 + off];
    const float* W1   = (const float*)d_in[7 + off];
    const float* as1  = (const float*)d_in[8 + off];
    const float* ad1  = (const float*)d_in[9 + off];
    const float* b1   = (const float*)d_in[10 + off];
    const float* W2   = (const float*)d_in[11 + off];
    const float* as2  = (const float*)d_in[12 + off];
    const float* ad2  = (const float*)d_in[13 + off];
    const float* b2   = (const float*)d_in[14 + off];
    const float* bng0 = (const float*)d_in[15 + off];
    const float* bnb0 = (const float*)d_in[16 + off];
    const float* bnm0 = (const float*)d_in[17 + off];
    const float* bnv0 = (const float*)d_in[18 + off];
    const float* bng1 = (const float*)d_in[19 + off];
    const float* bnb1 = (const float*)d_in[20 + off];
    const float* bnm1 = (const float*)d_in[21 + off];
    const float* bnv1 = (const float*)d_in[22 + off];
    const float* kk   = (const float*)d_in[23 + off];
    const float* dd   = (const float*)d_in[24 + off];
    const float* t00  = (const float*)d_in[25 + off];
    const float* u00  = (const float*)d_in[26 + off];
    const float* t    = (const float*)d_in[27 + off];
    float* out = (float*)d_out;

    int n = in_sizes[0] / 2;
    int e = in_sizes[1] / 2;
    int m = e + n;

    const int B = 256;
    auto nb = [](long long x_, int b) { return (int)((x_ + b - 1) / b); };
    int nwb = nb((long long)n * 32, B);   // warp-per-node grids

    cudaFuncSetAttribute(k_gemm_mma, cudaFuncAttributeMaxDynamicSharedMemorySize, MMA_SMEM);

    // CSR build + attention-vector precompute
    k_count<<<nb(m, B), B>>>(ei, e, m);
    k_scan<<<1, 1024>>>(n, m);
    k_fill<<<nb(m, B), B>>>(ei, e, m);
    k_pre<<<130, 256>>>(W0, as0, ad0, W1, as1, ad1);

    // ---- layer 0 (h never materialized; layer-1 scores fused into epilogue) ----
    k_score0<<<nb(n, B), B>>>(x, n);
    k_l0agg<<<nwb, B>>>(x, W0, b0, bng0, bnb0, bnm0, bnv0, n);

    // ---- layer 1 (aggregate z first, project after on tensor cores) ----
    k_agg1<<<nwb, B>>>(n);
    k_gemm_mma<<<nb(n, 128), 256, MMA_SMEM>>>(W1, b1, bng1, bnb1, bnm1, bnv1, n);

    // ---- layer 2 + epilogue ----
    k_l2<<<nwb, B>>>(W2, as2, ad2, n);
    k_smax2epi<<<nwb, B>>>(b2, kk, dd, t00, u00, t, out, n);
}